// round 8
// baseline (speedup 1.0000x reference)
#include <cuda_runtime.h>
#include <cuda_bf16.h>
#include <math.h>

#define NN 100000
#define NE 1600000
#define NG 100
#define NH 8
#define NC 16
#define NF 128

// ---------------- scratch (static device globals) ---------------------------
__device__ __align__(16) __nv_bfloat16 g_hb[(size_t)NN * NF];  // 25.6 MB h (bf16)
__device__ __align__(16) float g_asrc[NN * NH];
__device__ __align__(16) float g_adst[NN * NH];
__device__ __align__(16) float g_s[NN * NH];           // softmax denom, then inverted
__device__ __align__(16) float g_acc[NN * NC];         // head-averaged message accum
__device__ __align__(16) float g_colsum[NF];
__device__ __align__(16) float g_colsq[NF];
__device__ __align__(16) float g_scale[NF];
__device__ __align__(16) float g_shift[NF];
__device__ __align__(16) float g_pool[NG * NC];
__device__ __align__(16) float g_cnt[NG];

// vector reductions (no return) ---------------------------------------------
__device__ __forceinline__ void red_v4(float* p, float a, float b, float c, float d) {
    asm volatile("red.global.add.v4.f32 [%0], {%1, %2, %3, %4};"
                 :: "l"(p), "f"(a), "f"(b), "f"(c), "f"(d) : "memory");
}
__device__ __forceinline__ void red_v2(float* p, float a, float b) {
    asm volatile("red.global.add.v2.f32 [%0], {%1, %2};"
                 :: "l"(p), "f"(a), "f"(b) : "memory");
}

// ---------------- K0: zero accumulators ------------------------------------
__global__ void k_zero() {
    int i = blockIdx.x * blockDim.x + threadIdx.x;
    int st = gridDim.x * blockDim.x;
    for (int k = i; k < NN * NC; k += st) g_acc[k] = 0.f;
    if (i < NF) { g_colsum[i] = 0.f; g_colsq[i] = 0.f; }
    if (i < NG * NC) g_pool[i] = 0.f;
    if (i < NG) g_cnt[i] = 0.f;
}

// ---------------- K1: BN column stats --------------------------------------
__global__ void k_stats(const float* __restrict__ x) {
    __shared__ float ssum[NF];
    __shared__ float ssq[NF];
    int t = threadIdx.x;
    int lane = t & 31;
    int warp = t >> 5;
    int col = lane * 4;
    if (t < NF) { ssum[t] = 0.f; ssq[t] = 0.f; }
    __syncthreads();

    float s0 = 0.f, s1 = 0.f, s2 = 0.f, s3 = 0.f;
    float q0 = 0.f, q1 = 0.f, q2 = 0.f, q3 = 0.f;
    int row = blockIdx.x * 8 + warp;
    int step = gridDim.x * 8;
    for (int r = row; r < NN; r += step) {
        float4 v = *(const float4*)(x + (size_t)r * NF + col);
        s0 += v.x; s1 += v.y; s2 += v.z; s3 += v.w;
        q0 += v.x * v.x; q1 += v.y * v.y; q2 += v.z * v.z; q3 += v.w * v.w;
    }
    atomicAdd(&ssum[col + 0], s0); atomicAdd(&ssum[col + 1], s1);
    atomicAdd(&ssum[col + 2], s2); atomicAdd(&ssum[col + 3], s3);
    atomicAdd(&ssq[col + 0], q0);  atomicAdd(&ssq[col + 1], q1);
    atomicAdd(&ssq[col + 2], q2);  atomicAdd(&ssq[col + 3], q3);
    __syncthreads();
    if (t < NF) {
        atomicAdd(&g_colsum[t], ssum[t]);
        atomicAdd(&g_colsq[t], ssq[t]);
    }
}

// ---------------- K2: finalize BN scale/shift ------------------------------
__global__ void k_bnfin(const float* __restrict__ gamma, const float* __restrict__ beta) {
    int t = threadIdx.x;
    if (t < NF) {
        float mean = g_colsum[t] * (1.f / NN);
        float var = g_colsq[t] * (1.f / NN) - mean * mean;
        float sc = gamma[t] * rsqrtf(var + 1e-5f);
        g_scale[t] = sc;
        g_shift[t] = beta[t] - mean * sc;
    }
}

// ---------------- K3: fused BN + GEMM + attention logits --------------------
// 128 nodes/block, 256 threads, 8x8 microtile, KCH=64 (2 CTAs/SM).
#define KCH 64
#define SXT_STRIDE 132                           // 528 B/row = 33*16 (16B aligned)
#define SXT_FLOATS (KCH * SXT_STRIDE)
#define SW_FLOATS (KCH * 128)
#define GEMM_SMEM_BYTES ((SXT_FLOATS + SW_FLOATS) * 4)

__global__ void __launch_bounds__(256, 2)
k_gemm(const float* __restrict__ x, const float* __restrict__ W,
       const float* __restrict__ attS, const float* __restrict__ attD) {
    extern __shared__ float sm[];
    float* sxT = sm;                 // [k][row] stride 132
    float* sw = sm + SXT_FLOATS;     // [k][col]

    int t = threadIdx.x;
    int r0 = blockIdx.x * 128;
    int j = t & 15, i4 = t >> 4;

    float acc[8][8];
#pragma unroll
    for (int m = 0; m < 8; ++m)
#pragma unroll
        for (int n = 0; n < 8; ++n) acc[m][n] = 0.f;

    for (int k0 = 0; k0 < NF; k0 += KCH) {
        for (int i = t; i < SW_FLOATS / 4; i += 256)
            ((float4*)sw)[i] = ((const float4*)(W + (size_t)k0 * 128))[i];
        for (int i = t; i < 128 * KCH; i += 256) {
            int row = i >> 6, col = i & 63;
            int n = r0 + row;
            float v = 0.f;
            if (n < NN) v = x[(size_t)n * NF + k0 + col] * g_scale[k0 + col] + g_shift[k0 + col];
            sxT[col * SXT_STRIDE + row] = v;
        }
        __syncthreads();

        const float* aBase = sxT + i4 * 8;
        const float* bBase = sw + j * 8;
#pragma unroll 4
        for (int k = 0; k < KCH; ++k) {
            float4 a0 = *(const float4*)(aBase + k * SXT_STRIDE);
            float4 a1 = *(const float4*)(aBase + k * SXT_STRIDE + 4);
            float4 b0 = *(const float4*)(bBase + k * 128);
            float4 b1 = *(const float4*)(bBase + k * 128 + 4);
            float a[8] = {a0.x, a0.y, a0.z, a0.w, a1.x, a1.y, a1.z, a1.w};
            float b[8] = {b0.x, b0.y, b0.z, b0.w, b1.x, b1.y, b1.z, b1.w};
#pragma unroll
            for (int m = 0; m < 8; ++m)
#pragma unroll
                for (int n = 0; n < 8; ++n) acc[m][n] = fmaf(a[m], b[n], acc[m][n]);
        }
        __syncthreads();
    }

    int rowsValid = NN - r0;
    if (rowsValid > 128) rowsValid = 128;

    // store h tile as bf16 straight from registers
#pragma unroll
    for (int m = 0; m < 8; ++m) {
        int row = i4 * 8 + m;
        if (row < rowsValid) {
            __nv_bfloat162 p[4];
#pragma unroll
            for (int c = 0; c < 4; ++c)
                p[c] = __float22bfloat162_rn(make_float2(acc[m][2 * c], acc[m][2 * c + 1]));
            *(uint4*)(g_hb + (size_t)(r0 + row) * NF + j * 8) = *(uint4*)p;
        }
    }

    // attention logits from fp32 regs: thread covers half of head hh=j>>1
    int hh = j >> 1;
    float asv[8], adv[8];
#pragma unroll
    for (int c = 0; c < 8; ++c) {
        asv[c] = attS[hh * 16 + (j & 1) * 8 + c];
        adv[c] = attD[hh * 16 + (j & 1) * 8 + c];
    }
#pragma unroll
    for (int m = 0; m < 8; ++m) {
        float ps = 0.f, pd = 0.f;
#pragma unroll
        for (int c = 0; c < 8; ++c) {
            ps = fmaf(acc[m][c], asv[c], ps);
            pd = fmaf(acc[m][c], adv[c], pd);
        }
        ps += __shfl_xor_sync(0xffffffffu, ps, 1);
        pd += __shfl_xor_sync(0xffffffffu, pd, 1);
        int row = i4 * 8 + m;
        if ((j & 1) == 0 && row < rowsValid) {
            int n = r0 + row;
            g_asrc[n * NH + hh] = ps;
            g_adst[n * NH + hh] = pd;
            float e = ps + pd;
            e = e > 0.f ? e : 0.2f * e;
            g_s[n * NH + hh] = __expf(e);   // self-loop contribution
        }
    }
}

// ---------------- K4: edge pass 1 — denominators (4 threads/edge) ----------
__device__ __forceinline__ float lrelu_exp(float a, float b) {
    float e = a + b;
    e = e > 0.f ? e : 0.2f * e;
    return __expf(e);
}

__global__ void k_edge_s(const int* __restrict__ ei) {
    int gt = blockIdx.x * blockDim.x + threadIdx.x;
    int e = gt >> 2, q = gt & 3;
    if (e >= NE) return;
    int s = ei[e];
    int d = ei[NE + e];
    float2 a2 = *(const float2*)(g_asrc + s * NH + q * 2);
    float2 b2 = *(const float2*)(g_adst + d * NH + q * 2);
    red_v2(g_s + d * NH + q * 2, lrelu_exp(a2.x, b2.x), lrelu_exp(a2.y, b2.y));
}

// ---------------- K4b: invert denominators ---------------------------------
__global__ void k_sinv() {
    int i = blockIdx.x * blockDim.x + threadIdx.x;
    if (i < NN * NH) g_s[i] = __frcp_rn(g_s[i]);
}

// ---------------- K5: edge pass 2 — message scatter (4 threads/edge) -------
// Thread q handles heads {2q, 2q+1}: computes their alphas (2 exps, 24B
// gathered), loads their full 16-channel h rows via LDG.128, accumulates a
// 16-channel partial, butterfly-reduces across the 4 lanes, then REDs its
// 4-channel quarter.
__global__ void k_edge_msg(const int* __restrict__ ei) {
    int gt = blockIdx.x * blockDim.x + threadIdx.x;
    int e = gt >> 2, q = gt & 3;
    if (e >= NE) return;
    int s = ei[e];
    int d = ei[NE + e];

    // alphas for heads 2q, 2q+1
    float2 as2 = *(const float2*)(g_asrc + s * NH + q * 2);
    float2 ad2 = *(const float2*)(g_adst + d * NH + q * 2);
    float2 si2 = *(const float2*)(g_s + d * NH + q * 2);
    float alA = 0.125f * lrelu_exp(as2.x, ad2.x) * si2.x;
    float alB = 0.125f * lrelu_exp(as2.y, ad2.y) * si2.y;

    // h rows for heads 2q (A) and 2q+1 (B): 32B each = 2 x LDG.128
    const __nv_bfloat16* hrow = g_hb + (size_t)s * NF;
    uint4 uA0 = *(const uint4*)(hrow + (2 * q) * 16);
    uint4 uA1 = *(const uint4*)(hrow + (2 * q) * 16 + 8);
    uint4 uB0 = *(const uint4*)(hrow + (2 * q + 1) * 16);
    uint4 uB1 = *(const uint4*)(hrow + (2 * q + 1) * 16 + 8);

    float r[NC];
    const __nv_bfloat162* pA0 = (const __nv_bfloat162*)&uA0;
    const __nv_bfloat162* pA1 = (const __nv_bfloat162*)&uA1;
    const __nv_bfloat162* pB0 = (const __nv_bfloat162*)&uB0;
    const __nv_bfloat162* pB1 = (const __nv_bfloat162*)&uB1;
#pragma unroll
    for (int i = 0; i < 4; ++i) {
        float2 fA0 = __bfloat1622float2(pA0[i]);
        float2 fA1 = __bfloat1622float2(pA1[i]);
        float2 fB0 = __bfloat1622float2(pB0[i]);
        float2 fB1 = __bfloat1622float2(pB1[i]);
        r[2 * i + 0] = fmaf(alA, fA0.x, alB * fB0.x);
        r[2 * i + 1] = fmaf(alA, fA0.y, alB * fB0.y);
        r[8 + 2 * i + 0] = fmaf(alA, fA1.x, alB * fB1.x);
        r[8 + 2 * i + 1] = fmaf(alA, fA1.y, alB * fB1.y);
    }

    // butterfly-reduce the 16-channel partials across the 4 lanes of this edge
#pragma unroll
    for (int i = 0; i < 8; ++i) {
        float2 v = make_float2(r[2 * i], r[2 * i + 1]);
        unsigned long long uv = *(unsigned long long*)&v;
        unsigned long long o1 = __shfl_xor_sync(0xffffffffu, uv, 1);
        float2 f1 = *(float2*)&o1;
        v.x += f1.x; v.y += f1.y;
        uv = *(unsigned long long*)&v;
        unsigned long long o2 = __shfl_xor_sync(0xffffffffu, uv, 2);
        float2 f2 = *(float2*)&o2;
        r[2 * i] = v.x + f2.x;
        r[2 * i + 1] = v.y + f2.y;
    }

    // thread q scatters channels [4q, 4q+4)
    float* op = g_acc + (size_t)d * NC + q * 4;
    red_v4(op, r[4 * q + 0], r[4 * q + 1], r[4 * q + 2], r[4 * q + 3]);
}

// ---------------- K6: node finalize (self-loop + bias + ELU + pool) --------
__global__ void k_node_final(const int* __restrict__ batch,
                             const float* __restrict__ bias) {
    int gt = blockIdx.x * blockDim.x + threadIdx.x;
    int n = gt >> 4, c = gt & 15;
    if (n >= NN) return;
    float v = g_acc[n * NC + c];
    const __nv_bfloat16* hr = g_hb + (size_t)n * NF;
#pragma unroll
    for (int h = 0; h < NH; ++h) {
        float a = g_asrc[n * NH + h] + g_adst[n * NH + h];
        a = a > 0.f ? a : 0.2f * a;
        float w = __expf(a) * g_s[n * NH + h];   // g_s holds 1/s
        v = fmaf(0.125f * w, __bfloat162float(hr[h * 16 + c]), v);
    }
    v += bias[c];
    v = v > 0.f ? v : expm1f(v);
    int b = batch[n];
    atomicAdd(&g_pool[b * NC + c], v);
    if (c == 0) atomicAdd(&g_cnt[b], 1.0f);
}

// ---------------- K7: pooled mean ------------------------------------------
__global__ void k_pool_div(float* __restrict__ out) {
    int i = blockIdx.x * blockDim.x + threadIdx.x;
    if (i < NG * NC) {
        int g = i >> 4;
        out[i] = g_pool[i] / fmaxf(g_cnt[g], 1.0f);
    }
}

// ---------------- launch ----------------------------------------------------
extern "C" void kernel_launch(void* const* d_in, const int* in_sizes, int n_in,
                              void* d_out, int out_size) {
    const float* x = (const float*)d_in[0];
    const int* ei = (const int*)d_in[1];
    const int* batch = (const int*)d_in[2];
    const float* gamma = (const float*)d_in[3];
    const float* beta = (const float*)d_in[4];
    const float* W = (const float*)d_in[5];
    const float* attS = (const float*)d_in[6];
    const float* attD = (const float*)d_in[7];
    const float* bias = (const float*)d_in[8];
    float* out = (float*)d_out;

    cudaFuncSetAttribute(k_gemm, cudaFuncAttributeMaxDynamicSharedMemorySize,
                         GEMM_SMEM_BYTES);

    k_zero<<<256, 256>>>();
    k_stats<<<512, 256>>>(x);
    k_bnfin<<<1, 128>>>(gamma, beta);
    k_gemm<<<(NN + 127) / 128, 256, GEMM_SMEM_BYTES>>>(x, W, attS, attD);
    k_edge_s<<<(NE * 4 + 255) / 256, 256>>>(ei);
    k_sinv<<<(NN * NH + 255) / 256, 256>>>();
    k_edge_msg<<<(NE * 4 + 255) / 256, 256>>>(ei);
    k_node_final<<<(NN * 16 + 255) / 256, 256>>>(batch, bias);
    k_pool_div<<<(NG * NC + 255) / 256, 256>>>(out);
}

// round 9
// speedup vs baseline: 1.1324x; 1.1324x over previous
#include <cuda_runtime.h>
#include <cuda_bf16.h>
#include <math.h>

#define NN 100000
#define NE 1600000
#define NG 100
#define NH 8
#define NC 16
#define NF 128

// ---------------- scratch (static device globals) ---------------------------
__device__ __align__(16) __nv_bfloat16 g_hb[(size_t)NN * NF];  // 25.6 MB h (bf16)
__device__ __align__(16) float g_asrc[NN * NH];
__device__ __align__(16) float g_adst[NN * NH];
__device__ __align__(16) float g_s[NN * NH];           // softmax denom, then inverted
__device__ __align__(16) float g_acc[NN * NC];         // head-averaged message accum
__device__ __align__(16) float g_colsum[NF];
__device__ __align__(16) float g_colsq[NF];
__device__ __align__(16) float g_scale[NF];
__device__ __align__(16) float g_shift[NF];
__device__ __align__(16) float g_pool[NG * NC];
__device__ __align__(16) float g_cnt[NG];

// vector reduction (no return) ----------------------------------------------
__device__ __forceinline__ void red_v4(float* p, float a, float b, float c, float d) {
    asm volatile("red.global.add.v4.f32 [%0], {%1, %2, %3, %4};"
                 :: "l"(p), "f"(a), "f"(b), "f"(c), "f"(d) : "memory");
}

__device__ __forceinline__ unsigned f2tf32(float f) {
    unsigned r;
    asm("cvt.rna.tf32.f32 %0, %1;" : "=r"(r) : "f"(f));
    return r;
}

// ---------------- K0: zero accumulators ------------------------------------
__global__ void k_zero() {
    int i = blockIdx.x * blockDim.x + threadIdx.x;
    int st = gridDim.x * blockDim.x;
    for (int k = i; k < NN * NC; k += st) g_acc[k] = 0.f;
    if (i < NF) { g_colsum[i] = 0.f; g_colsq[i] = 0.f; }
    if (i < NG * NC) g_pool[i] = 0.f;
    if (i < NG) g_cnt[i] = 0.f;
}

// ---------------- K1: BN column stats --------------------------------------
__global__ void k_stats(const float* __restrict__ x) {
    __shared__ float ssum[NF];
    __shared__ float ssq[NF];
    int t = threadIdx.x;
    int lane = t & 31;
    int warp = t >> 5;
    int col = lane * 4;
    if (t < NF) { ssum[t] = 0.f; ssq[t] = 0.f; }
    __syncthreads();

    float s0 = 0.f, s1 = 0.f, s2 = 0.f, s3 = 0.f;
    float q0 = 0.f, q1 = 0.f, q2 = 0.f, q3 = 0.f;
    int row = blockIdx.x * 8 + warp;
    int step = gridDim.x * 8;
    for (int r = row; r < NN; r += step) {
        float4 v = *(const float4*)(x + (size_t)r * NF + col);
        s0 += v.x; s1 += v.y; s2 += v.z; s3 += v.w;
        q0 += v.x * v.x; q1 += v.y * v.y; q2 += v.z * v.z; q3 += v.w * v.w;
    }
    atomicAdd(&ssum[col + 0], s0); atomicAdd(&ssum[col + 1], s1);
    atomicAdd(&ssum[col + 2], s2); atomicAdd(&ssum[col + 3], s3);
    atomicAdd(&ssq[col + 0], q0);  atomicAdd(&ssq[col + 1], q1);
    atomicAdd(&ssq[col + 2], q2);  atomicAdd(&ssq[col + 3], q3);
    __syncthreads();
    if (t < NF) {
        atomicAdd(&g_colsum[t], ssum[t]);
        atomicAdd(&g_colsq[t], ssq[t]);
    }
}

// ---------------- K2: finalize BN scale/shift ------------------------------
__global__ void k_bnfin(const float* __restrict__ gamma, const float* __restrict__ beta) {
    int t = threadIdx.x;
    if (t < NF) {
        float mean = g_colsum[t] * (1.f / NN);
        float var = g_colsq[t] * (1.f / NN) - mean * mean;
        float sc = gamma[t] * rsqrtf(var + 1e-5f);
        g_scale[t] = sc;
        g_shift[t] = beta[t] - mean * sc;
    }
}

// ---------------- K3: tensor-core (tf32 mma) BN + GEMM + logits -------------
// 128x128 tile per block, 8 warps; warp (wm,wn) computes 64x32 via 4x4
// m16n8k8 mma fragments. K chunked by 32 through smem (tf32).
#define XS_STRIDE 36
#define WS_STRIDE 136

#define MMA_TF32(d, a, b)                                                     \
    asm volatile(                                                             \
        "mma.sync.aligned.m16n8k8.row.col.f32.tf32.tf32.f32 "                 \
        "{%0,%1,%2,%3}, {%4,%5,%6,%7}, {%8,%9}, {%0,%1,%2,%3};"               \
        : "+f"(d[0]), "+f"(d[1]), "+f"(d[2]), "+f"(d[3])                      \
        : "r"(a[0]), "r"(a[1]), "r"(a[2]), "r"(a[3]), "r"(b[0]), "r"(b[1]))

__global__ void __launch_bounds__(256, 2)
k_gemm(const float* __restrict__ x, const float* __restrict__ W,
       const float* __restrict__ attS, const float* __restrict__ attD) {
    __shared__ unsigned Xs[128 * XS_STRIDE];   // [row][k] tf32
    __shared__ unsigned Ws[32 * WS_STRIDE];    // [k][n] tf32

    int t = threadIdx.x;
    int lane = t & 31;
    int wid = t >> 5;
    int g = lane >> 2, tg = lane & 3;
    int wm = wid & 1, wn = wid >> 1;           // 2 x 4 warp grid
    int r0 = blockIdx.x * 128;

    float acc[4][4][4];
#pragma unroll
    for (int i = 0; i < 4; ++i)
#pragma unroll
        for (int j = 0; j < 4; ++j)
#pragma unroll
            for (int c = 0; c < 4; ++c) acc[i][j][c] = 0.f;

    for (int kc = 0; kc < NF; kc += 32) {
        // stage X chunk [128 rows][32 k] (BN applied, tf32)
#pragma unroll
        for (int p = 0; p < 16; ++p) {
            int i = t + p * 256;
            int row = i >> 5, col = i & 31;
            int n = r0 + row, k = kc + col;
            float v = 0.f;
            if (n < NN) v = x[(size_t)n * NF + k] * g_scale[k] + g_shift[k];
            Xs[row * XS_STRIDE + col] = f2tf32(v);
        }
        // stage W chunk [32 k][128 n] (tf32)
#pragma unroll
        for (int p = 0; p < 16; ++p) {
            int i = t + p * 256;
            int row = i >> 7, col = i & 127;
            Ws[row * WS_STRIDE + col] = f2tf32(W[(size_t)(kc + row) * NF + col]);
        }
        __syncthreads();

#pragma unroll
        for (int ks = 0; ks < 4; ++ks) {
            int k = ks * 8;
            unsigned a[4][4], b[4][2];
#pragma unroll
            for (int i = 0; i < 4; ++i) {
                int rlo = wm * 64 + i * 16 + g;
                a[i][0] = Xs[rlo * XS_STRIDE + k + tg];
                a[i][1] = Xs[(rlo + 8) * XS_STRIDE + k + tg];
                a[i][2] = Xs[rlo * XS_STRIDE + k + tg + 4];
                a[i][3] = Xs[(rlo + 8) * XS_STRIDE + k + tg + 4];
            }
#pragma unroll
            for (int j = 0; j < 4; ++j) {
                int c = wn * 32 + j * 8 + g;
                b[j][0] = Ws[(k + tg) * WS_STRIDE + c];
                b[j][1] = Ws[(k + tg + 4) * WS_STRIDE + c];
            }
#pragma unroll
            for (int i = 0; i < 4; ++i)
#pragma unroll
                for (int j = 0; j < 4; ++j) MMA_TF32(acc[i][j], a[i], b[j]);
        }
        __syncthreads();
    }

    int rowsValid = NN - r0;
    if (rowsValid > 128) rowsValid = 128;

    // store h tile as bf16 from fragments
#pragma unroll
    for (int i = 0; i < 4; ++i) {
        int rlo = wm * 64 + i * 16 + g;
        int rhi = rlo + 8;
#pragma unroll
        for (int j = 0; j < 4; ++j) {
            int c0 = wn * 32 + j * 8 + 2 * tg;
            if (rlo < rowsValid) {
                __nv_bfloat162 p = __float22bfloat162_rn(
                    make_float2(acc[i][j][0], acc[i][j][1]));
                *(__nv_bfloat162*)(g_hb + (size_t)(r0 + rlo) * NF + c0) = p;
            }
            if (rhi < rowsValid) {
                __nv_bfloat162 p = __float22bfloat162_rn(
                    make_float2(acc[i][j][2], acc[i][j][3]));
                *(__nv_bfloat162*)(g_hb + (size_t)(r0 + rhi) * NF + c0) = p;
            }
        }
    }

    // attention logits: warp covers heads {2wn, 2wn+1}; quad-reduce over tg
    float aS[2][2][2], aD[2][2][2];  // [headLocal][j2][pairElem]
#pragma unroll
    for (int hl = 0; hl < 2; ++hl)
#pragma unroll
        for (int j2 = 0; j2 < 2; ++j2) {
            int base = (2 * wn + hl) * 16 + j2 * 8 + 2 * tg;
            aS[hl][j2][0] = attS[base];     aS[hl][j2][1] = attS[base + 1];
            aD[hl][j2][0] = attD[base];     aD[hl][j2][1] = attD[base + 1];
        }

#pragma unroll
    for (int i = 0; i < 4; ++i) {
#pragma unroll
        for (int hl = 0; hl < 2; ++hl) {
            float psl = 0.f, pdl = 0.f, psh = 0.f, pdh = 0.f;
#pragma unroll
            for (int j2 = 0; j2 < 2; ++j2) {
                int j = 2 * hl + j2;
                psl = fmaf(acc[i][j][0], aS[hl][j2][0],
                      fmaf(acc[i][j][1], aS[hl][j2][1], psl));
                pdl = fmaf(acc[i][j][0], aD[hl][j2][0],
                      fmaf(acc[i][j][1], aD[hl][j2][1], pdl));
                psh = fmaf(acc[i][j][2], aS[hl][j2][0],
                      fmaf(acc[i][j][3], aS[hl][j2][1], psh));
                pdh = fmaf(acc[i][j][2], aD[hl][j2][0],
                      fmaf(acc[i][j][3], aD[hl][j2][1], pdh));
            }
            // reduce within quad (lanes differing in tg only)
            psl += __shfl_xor_sync(0xffffffffu, psl, 1);
            psl += __shfl_xor_sync(0xffffffffu, psl, 2);
            pdl += __shfl_xor_sync(0xffffffffu, pdl, 1);
            pdl += __shfl_xor_sync(0xffffffffu, pdl, 2);
            psh += __shfl_xor_sync(0xffffffffu, psh, 1);
            psh += __shfl_xor_sync(0xffffffffu, psh, 2);
            pdh += __shfl_xor_sync(0xffffffffu, pdh, 1);
            pdh += __shfl_xor_sync(0xffffffffu, pdh, 2);
            if (tg == 0) {
                int h = 2 * wn + hl;
                int rlo = wm * 64 + i * 16 + g;
                int rhi = rlo + 8;
                if (rlo < rowsValid) {
                    int n = r0 + rlo;
                    g_asrc[n * NH + h] = psl;
                    g_adst[n * NH + h] = pdl;
                    float e = psl + pdl;
                    e = e > 0.f ? e : 0.2f * e;
                    g_s[n * NH + h] = __expf(e);
                }
                if (rhi < rowsValid) {
                    int n = r0 + rhi;
                    g_asrc[n * NH + h] = psh;
                    g_adst[n * NH + h] = pdh;
                    float e = psh + pdh;
                    e = e > 0.f ? e : 0.2f * e;
                    g_s[n * NH + h] = __expf(e);
                }
            }
        }
    }
}

// ---------------- K4: edge pass 1 — softmax denominators (R7 form) ---------
__device__ __forceinline__ float lrelu_exp(float a, float b) {
    float e = a + b;
    e = e > 0.f ? e : 0.2f * e;
    return __expf(e);
}

__global__ void k_edge_s(const int* __restrict__ ei) {
    int e = blockIdx.x * blockDim.x + threadIdx.x;
    if (e >= NE) return;
    int s = ei[e];
    int d = ei[NE + e];
    float4 a0 = *(const float4*)(g_asrc + s * NH);
    float4 a1 = *(const float4*)(g_asrc + s * NH + 4);
    float4 b0 = *(const float4*)(g_adst + d * NH);
    float4 b1 = *(const float4*)(g_adst + d * NH + 4);
    float* sp = g_s + d * NH;
    red_v4(sp, lrelu_exp(a0.x, b0.x), lrelu_exp(a0.y, b0.y),
               lrelu_exp(a0.z, b0.z), lrelu_exp(a0.w, b0.w));
    red_v4(sp + 4, lrelu_exp(a1.x, b1.x), lrelu_exp(a1.y, b1.y),
                   lrelu_exp(a1.z, b1.z), lrelu_exp(a1.w, b1.w));
}

// ---------------- K4b: invert denominators ---------------------------------
__global__ void k_sinv() {
    int i = blockIdx.x * blockDim.x + threadIdx.x;
    if (i < NN * NH) g_s[i] = __frcp_rn(g_s[i]);
}

// ---------------- K5: edge pass 2 — message scatter (R7 form) --------------
// 4 threads/edge; thread q computes alpha for head-pair q, pairs exchanged
// via shfl_xor, each thread fmas its 4 output channels.
__global__ void k_edge_msg(const int* __restrict__ ei) {
    int gt = blockIdx.x * blockDim.x + threadIdx.x;
    int e = gt >> 2, q = gt & 3;
    if (e >= NE) return;
    int s = ei[e];
    int d = ei[NE + e];

    float2 as2 = *(const float2*)(g_asrc + s * NH + q * 2);
    float2 ad2 = *(const float2*)(g_adst + d * NH + q * 2);
    float2 si2 = *(const float2*)(g_s + d * NH + q * 2);
    float2 alq;
    alq.x = 0.125f * lrelu_exp(as2.x, ad2.x) * si2.x;
    alq.y = 0.125f * lrelu_exp(as2.y, ad2.y) * si2.y;

    unsigned long long v0 = *(unsigned long long*)&alq;
    unsigned long long v1 = __shfl_xor_sync(0xffffffffu, v0, 1);
    unsigned long long v2 = __shfl_xor_sync(0xffffffffu, v0, 2);
    unsigned long long v3 = __shfl_xor_sync(0xffffffffu, v1, 2);
    float2 p1 = *(float2*)&v1, p2 = *(float2*)&v2, p3 = *(float2*)&v3;

    float al[8];
#pragma unroll
    for (int i = 0; i < 4; ++i) {
        int r = i ^ q;
        float2 p = (r == 0) ? alq : (r == 1) ? p1 : (r == 2) ? p2 : p3;
        al[2 * i] = p.x;
        al[2 * i + 1] = p.y;
    }

    const __nv_bfloat16* hrow = g_hb + (size_t)s * NF + q * 4;
    float r0 = 0.f, r1 = 0.f, r2 = 0.f, r3 = 0.f;
#pragma unroll
    for (int h = 0; h < NH; ++h) {
        __nv_bfloat162 p01 = *(const __nv_bfloat162*)(hrow + h * 16);
        __nv_bfloat162 p23 = *(const __nv_bfloat162*)(hrow + h * 16 + 2);
        float2 f01 = __bfloat1622float2(p01);
        float2 f23 = __bfloat1622float2(p23);
        r0 = fmaf(al[h], f01.x, r0);
        r1 = fmaf(al[h], f01.y, r1);
        r2 = fmaf(al[h], f23.x, r2);
        r3 = fmaf(al[h], f23.y, r3);
    }
    red_v4(g_acc + d * NC + q * 4, r0, r1, r2, r3);
}

// ---------------- K6: node finalize (self-loop + bias + ELU + pool) --------
__global__ void k_node_final(const int* __restrict__ batch,
                             const float* __restrict__ bias) {
    int gt = blockIdx.x * blockDim.x + threadIdx.x;
    int n = gt >> 4, c = gt & 15;
    if (n >= NN) return;
    float v = g_acc[n * NC + c];
    const __nv_bfloat16* hr = g_hb + (size_t)n * NF;
#pragma unroll
    for (int h = 0; h < NH; ++h) {
        float a = g_asrc[n * NH + h] + g_adst[n * NH + h];
        a = a > 0.f ? a : 0.2f * a;
        float w = __expf(a) * g_s[n * NH + h];   // g_s holds 1/s
        v = fmaf(0.125f * w, __bfloat162float(hr[h * 16 + c]), v);
    }
    v += bias[c];
    v = v > 0.f ? v : expm1f(v);
    int b = batch[n];
    atomicAdd(&g_pool[b * NC + c], v);
    if (c == 0) atomicAdd(&g_cnt[b], 1.0f);
}

// ---------------- K7: pooled mean ------------------------------------------
__global__ void k_pool_div(float* __restrict__ out) {
    int i = blockIdx.x * blockDim.x + threadIdx.x;
    if (i < NG * NC) {
        int g = i >> 4;
        out[i] = g_pool[i] / fmaxf(g_cnt[g], 1.0f);
    }
}

// ---------------- launch ----------------------------------------------------
extern "C" void kernel_launch(void* const* d_in, const int* in_sizes, int n_in,
                              void* d_out, int out_size) {
    const float* x = (const float*)d_in[0];
    const int* ei = (const int*)d_in[1];
    const int* batch = (const int*)d_in[2];
    const float* gamma = (const float*)d_in[3];
    const float* beta = (const float*)d_in[4];
    const float* W = (const float*)d_in[5];
    const float* attS = (const float*)d_in[6];
    const float* attD = (const float*)d_in[7];
    const float* bias = (const float*)d_in[8];
    float* out = (float*)d_out;

    k_zero<<<256, 256>>>();
    k_stats<<<512, 256>>>(x);
    k_bnfin<<<1, 128>>>(gamma, beta);
    k_gemm<<<(NN + 127) / 128, 256>>>(x, W, attS, attD);
    k_edge_s<<<(NE + 255) / 256, 256>>>(ei);
    k_sinv<<<(NN * NH + 255) / 256, 256>>>();
    k_edge_msg<<<(NE * 4 + 255) / 256, 256>>>(ei);
    k_node_final<<<(NN * 16 + 255) / 256, 256>>>(batch, bias);
    k_pool_div<<<(NG * NC + 255) / 256, 256>>>(out);
}

// round 11
// speedup vs baseline: 1.2386x; 1.0938x over previous
#include <cuda_runtime.h>
#include <cuda_bf16.h>
#include <math.h>

#define NN 100000
#define NE 1600000
#define NG 100
#define NH 8
#define NC 16
#define NF 128

// ---------------- scratch (static device globals) ---------------------------
__device__ __align__(16) __nv_bfloat16 g_hb[(size_t)NN * NF];  // 25.6 MB h (bf16)
__device__ __align__(16) float g_asrc[NN * NH];
__device__ __align__(16) float g_adst[NN * NH];
__device__ __align__(16) float g_s[NN * NH];           // softmax denom, then inverted
__device__ __align__(16) float g_acc[NN * NC];         // head-averaged message accum
__device__ __align__(16) float g_colsum[NF];
__device__ __align__(16) float g_colsq[NF];
__device__ __align__(16) float g_scale[NF];
__device__ __align__(16) float g_shift[NF];
__device__ __align__(16) float g_Wp[NF * NF];          // BN-folded weights
__device__ __align__(16) float g_bp[NF];               // BN-folded bias
__device__ __align__(16) float g_pool[NG * NC];
__device__ __align__(16) float g_cnt[NG];

// vector reduction (no return) ----------------------------------------------
__device__ __forceinline__ void red_v4(float* p, float a, float b, float c, float d) {
    asm volatile("red.global.add.v4.f32 [%0], {%1, %2, %3, %4};"
                 :: "l"(p), "f"(a), "f"(b), "f"(c), "f"(d) : "memory");
}

__device__ __forceinline__ unsigned f2tf32(float f) {
    unsigned r;
    asm("cvt.rna.tf32.f32 %0, %1;" : "=r"(r) : "f"(f));
    return r;
}

// ---------------- K0: zero accumulators ------------------------------------
__global__ void k_zero() {
    int i = blockIdx.x * blockDim.x + threadIdx.x;
    int st = gridDim.x * blockDim.x;
    for (int k = i; k < NN * NC; k += st) g_acc[k] = 0.f;
    if (i < NF) { g_colsum[i] = 0.f; g_colsq[i] = 0.f; }
    if (i < NG * NC) g_pool[i] = 0.f;
    if (i < NG) g_cnt[i] = 0.f;
}

// ---------------- K1: BN column stats --------------------------------------
__global__ void k_stats(const float* __restrict__ x) {
    __shared__ float ssum[NF];
    __shared__ float ssq[NF];
    int t = threadIdx.x;
    int lane = t & 31;
    int warp = t >> 5;
    int col = lane * 4;
    if (t < NF) { ssum[t] = 0.f; ssq[t] = 0.f; }
    __syncthreads();

    float s0 = 0.f, s1 = 0.f, s2 = 0.f, s3 = 0.f;
    float q0 = 0.f, q1 = 0.f, q2 = 0.f, q3 = 0.f;
    int row = blockIdx.x * 8 + warp;
    int step = gridDim.x * 8;
    for (int r = row; r < NN; r += step) {
        float4 v = *(const float4*)(x + (size_t)r * NF + col);
        s0 += v.x; s1 += v.y; s2 += v.z; s3 += v.w;
        q0 += v.x * v.x; q1 += v.y * v.y; q2 += v.z * v.z; q3 += v.w * v.w;
    }
    atomicAdd(&ssum[col + 0], s0); atomicAdd(&ssum[col + 1], s1);
    atomicAdd(&ssum[col + 2], s2); atomicAdd(&ssum[col + 3], s3);
    atomicAdd(&ssq[col + 0], q0);  atomicAdd(&ssq[col + 1], q1);
    atomicAdd(&ssq[col + 2], q2);  atomicAdd(&ssq[col + 3], q3);
    __syncthreads();
    if (t < NF) {
        atomicAdd(&g_colsum[t], ssum[t]);
        atomicAdd(&g_colsq[t], ssq[t]);
    }
}

// ---------------- K2: finalize BN scale/shift ------------------------------
__global__ void k_bnfin(const float* __restrict__ gamma, const float* __restrict__ beta) {
    int t = threadIdx.x;
    if (t < NF) {
        float mean = g_colsum[t] * (1.f / NN);
        float var = g_colsq[t] * (1.f / NN) - mean * mean;
        float sc = gamma[t] * rsqrtf(var + 1e-5f);
        g_scale[t] = sc;
        g_shift[t] = beta[t] - mean * sc;
    }
}

// ---------------- K2b: fold BN into weights ---------------------------------
__global__ void k_prep(const float* __restrict__ W) {
    if (blockIdx.x < 64) {
        int i = blockIdx.x * 256 + threadIdx.x;
        int k = i >> 7;
        g_Wp[i] = g_scale[k] * W[i];
    } else if (threadIdx.x < NF) {
        int j = threadIdx.x;
        float b = 0.f;
        for (int k = 0; k < NF; ++k) b = fmaf(g_shift[k], W[k * NF + j], b);
        g_bp[j] = b;
    }
}

// ---------------- K3: tensor-core GEMM x@W' + b' + logits -------------------
// 128x128 tile/block, 8 warps, m16n8k8 tf32 mma. W' staged once (rna cvt at
// staging); x chunks cp.async double-buffered, rna-converted in smem.
#define XS_STRIDE 36
#define WS_STRIDE 136
#define XCHUNK_FLOATS (128 * XS_STRIDE)
#define WSM_FLOATS (NF * WS_STRIDE)
#define GEMM_SMEM_BYTES ((WSM_FLOATS + 2 * XCHUNK_FLOATS) * 4)

#define MMA_TF32(d, a, b)                                                     \
    asm volatile(                                                             \
        "mma.sync.aligned.m16n8k8.row.col.f32.tf32.tf32.f32 "                 \
        "{%0,%1,%2,%3}, {%4,%5,%6,%7}, {%8,%9}, {%0,%1,%2,%3};"               \
        : "+f"(d[0]), "+f"(d[1]), "+f"(d[2]), "+f"(d[3])                      \
        : "r"(a[0]), "r"(a[1]), "r"(a[2]), "r"(a[3]), "r"(b[0]), "r"(b[1]))

__device__ __forceinline__ void cp16(void* dst_smem, const void* src, int sz) {
    unsigned d = (unsigned)__cvta_generic_to_shared(dst_smem);
    asm volatile("cp.async.cg.shared.global [%0], [%1], 16, %2;"
                 :: "r"(d), "l"(src), "r"(sz));
}
#define CP_COMMIT() asm volatile("cp.async.commit_group;")

__global__ void __launch_bounds__(256, 2)
k_gemm(const float* __restrict__ x,
       const float* __restrict__ attS, const float* __restrict__ attD) {
    extern __shared__ float smem[];
    float* Wsm = smem;                       // [k][n] stride 136 (tf32 bits)
    float* Xs0 = smem + WSM_FLOATS;          // [row][k] stride 36, stage 0
    float* Xs1 = Xs0 + XCHUNK_FLOATS;        // stage 1

    int t = threadIdx.x;
    int lane = t & 31;
    int wid = t >> 5;
    int g = lane >> 2, tg = lane & 3;
    int wm = wid & 1, wn = wid >> 1;         // 2 x 4 warp grid
    int r0 = blockIdx.x * 128;

    // issue x chunk 0 (rows r0..r0+127, k 0..31)
#pragma unroll
    for (int p = 0; p < 4; ++p) {
        int idx = t + p * 256;
        int row = idx >> 3, grp = idx & 7;
        int n = r0 + row;
        cp16(Xs0 + row * XS_STRIDE + grp * 4,
             x + (size_t)n * NF + grp * 4, (n < NN) ? 16 : 0);
    }
    CP_COMMIT();

    // stage W' whole, rna-converted to tf32 at staging
#pragma unroll
    for (int p = 0; p < 16; ++p) {
        int i = t + p * 256;
        int row = i >> 5, grp = i & 31;
        float4 v = ((const float4*)(g_Wp + row * NF))[grp];
        unsigned* dst = (unsigned*)(Wsm + row * WS_STRIDE + grp * 4);
        dst[0] = f2tf32(v.x); dst[1] = f2tf32(v.y);
        dst[2] = f2tf32(v.z); dst[3] = f2tf32(v.w);
    }

    float acc[4][4][4];
#pragma unroll
    for (int i = 0; i < 4; ++i)
#pragma unroll
        for (int j = 0; j < 4; ++j)
#pragma unroll
            for (int c = 0; c < 4; ++c) acc[i][j][c] = 0.f;

#pragma unroll
    for (int kc = 0; kc < 4; ++kc) {
        // issue next chunk
        if (kc < 3) {
            float* Xs = (kc & 1) ? Xs0 : Xs1;   // next buffer
            int kbase = (kc + 1) * 32;
#pragma unroll
            for (int p = 0; p < 4; ++p) {
                int idx = t + p * 256;
                int row = idx >> 3, grp = idx & 7;
                int n = r0 + row;
                cp16(Xs + row * XS_STRIDE + grp * 4,
                     x + (size_t)n * NF + kbase + grp * 4, (n < NN) ? 16 : 0);
            }
            CP_COMMIT();
            asm volatile("cp.async.wait_group 1;");
        } else {
            asm volatile("cp.async.wait_group 0;");
        }
        __syncthreads();

        // in-place rna conversion of this chunk (16 elts/thread)
        float* Xsf = (kc & 1) ? Xs1 : Xs0;
        unsigned* Xsu = (unsigned*)Xsf;
#pragma unroll
        for (int p = 0; p < 16; ++p) {
            int idx = t + p * 256;              // 0..4095
            int row = idx >> 5, col = idx & 31;
            int a = row * XS_STRIDE + col;
            Xsu[a] = f2tf32(Xsf[a]);
        }
        __syncthreads();

        const unsigned* Xs = Xsu;
#pragma unroll
        for (int ks = 0; ks < 4; ++ks) {
            int k = ks * 8;
            unsigned a[4][4], b[4][2];
#pragma unroll
            for (int i = 0; i < 4; ++i) {
                int rlo = wm * 64 + i * 16 + g;
                a[i][0] = Xs[rlo * XS_STRIDE + k + tg];
                a[i][1] = Xs[(rlo + 8) * XS_STRIDE + k + tg];
                a[i][2] = Xs[rlo * XS_STRIDE + k + tg + 4];
                a[i][3] = Xs[(rlo + 8) * XS_STRIDE + k + tg + 4];
            }
#pragma unroll
            for (int j = 0; j < 4; ++j) {
                int c = wn * 32 + j * 8 + g;
                b[j][0] = __float_as_uint(Wsm[(kc * 32 + k + tg) * WS_STRIDE + c]);
                b[j][1] = __float_as_uint(Wsm[(kc * 32 + k + tg + 4) * WS_STRIDE + c]);
            }
#pragma unroll
            for (int i = 0; i < 4; ++i)
#pragma unroll
                for (int j = 0; j < 4; ++j) MMA_TF32(acc[i][j], a[i], b[j]);
        }
        __syncthreads();
    }

    int rowsValid = NN - r0;
    if (rowsValid > 128) rowsValid = 128;

    // add folded-BN bias b'[col]
#pragma unroll
    for (int j = 0; j < 4; ++j) {
        int c0 = wn * 32 + j * 8 + 2 * tg;
        float b0 = g_bp[c0], b1 = g_bp[c0 + 1];
#pragma unroll
        for (int i = 0; i < 4; ++i) {
            acc[i][j][0] += b0; acc[i][j][1] += b1;
            acc[i][j][2] += b0; acc[i][j][3] += b1;
        }
    }

    // store h tile as bf16 from fragments
#pragma unroll
    for (int i = 0; i < 4; ++i) {
        int rlo = wm * 64 + i * 16 + g;
        int rhi = rlo + 8;
#pragma unroll
        for (int j = 0; j < 4; ++j) {
            int c0 = wn * 32 + j * 8 + 2 * tg;
            if (rlo < rowsValid) {
                __nv_bfloat162 p = __float22bfloat162_rn(
                    make_float2(acc[i][j][0], acc[i][j][1]));
                *(__nv_bfloat162*)(g_hb + (size_t)(r0 + rlo) * NF + c0) = p;
            }
            if (rhi < rowsValid) {
                __nv_bfloat162 p = __float22bfloat162_rn(
                    make_float2(acc[i][j][2], acc[i][j][3]));
                *(__nv_bfloat162*)(g_hb + (size_t)(r0 + rhi) * NF + c0) = p;
            }
        }
    }

    // attention logits: warp covers heads {2wn, 2wn+1}; quad-reduce over tg
    float aS[2][2][2], aD[2][2][2];
#pragma unroll
    for (int hl = 0; hl < 2; ++hl)
#pragma unroll
        for (int j2 = 0; j2 < 2; ++j2) {
            int base = (2 * wn + hl) * 16 + j2 * 8 + 2 * tg;
            aS[hl][j2][0] = attS[base];     aS[hl][j2][1] = attS[base + 1];
            aD[hl][j2][0] = attD[base];     aD[hl][j2][1] = attD[base + 1];
        }

#pragma unroll
    for (int i = 0; i < 4; ++i) {
#pragma unroll
        for (int hl = 0; hl < 2; ++hl) {
            float psl = 0.f, pdl = 0.f, psh = 0.f, pdh = 0.f;
#pragma unroll
            for (int j2 = 0; j2 < 2; ++j2) {
                int j = 2 * hl + j2;
                psl = fmaf(acc[i][j][0], aS[hl][j2][0],
                      fmaf(acc[i][j][1], aS[hl][j2][1], psl));
                pdl = fmaf(acc[i][j][0], aD[hl][j2][0],
                      fmaf(acc[i][j][1], aD[hl][j2][1], pdl));
                psh = fmaf(acc[i][j][2], aS[hl][j2][0],
                      fmaf(acc[i][j][3], aS[hl][j2][1], psh));
                pdh = fmaf(acc[i][j][2], aD[hl][j2][0],
                      fmaf(acc[i][j][3], aD[hl][j2][1], pdh));
            }
            psl += __shfl_xor_sync(0xffffffffu, psl, 1);
            psl += __shfl_xor_sync(0xffffffffu, psl, 2);
            pdl += __shfl_xor_sync(0xffffffffu, pdl, 1);
            pdl += __shfl_xor_sync(0xffffffffu, pdl, 2);
            psh += __shfl_xor_sync(0xffffffffu, psh, 1);
            psh += __shfl_xor_sync(0xffffffffu, psh, 2);
            pdh += __shfl_xor_sync(0xffffffffu, pdh, 1);
            pdh += __shfl_xor_sync(0xffffffffu, pdh, 2);
            if (tg == 0) {
                int h = 2 * wn + hl;
                int rlo = wm * 64 + i * 16 + g;
                int rhi = rlo + 8;
                if (rlo < rowsValid) {
                    int n = r0 + rlo;
                    g_asrc[n * NH + h] = psl;
                    g_adst[n * NH + h] = pdl;
                    float e = psl + pdl;
                    e = e > 0.f ? e : 0.2f * e;
                    g_s[n * NH + h] = __expf(e);
                }
                if (rhi < rowsValid) {
                    int n = r0 + rhi;
                    g_asrc[n * NH + h] = psh;
                    g_adst[n * NH + h] = pdh;
                    float e = psh + pdh;
                    e = e > 0.f ? e : 0.2f * e;
                    g_s[n * NH + h] = __expf(e);
                }
            }
        }
    }
}

// ---------------- K4: edge pass 1 — softmax denominators -------------------
__device__ __forceinline__ float lrelu_exp(float a, float b) {
    float e = a + b;
    e = e > 0.f ? e : 0.2f * e;
    return __expf(e);
}

__global__ void k_edge_s(const int* __restrict__ ei) {
    int e = blockIdx.x * blockDim.x + threadIdx.x;
    if (e >= NE) return;
    int s = ei[e];
    int d = ei[NE + e];
    float4 a0 = *(const float4*)(g_asrc + s * NH);
    float4 a1 = *(const float4*)(g_asrc + s * NH + 4);
    float4 b0 = *(const float4*)(g_adst + d * NH);
    float4 b1 = *(const float4*)(g_adst + d * NH + 4);
    float* sp = g_s + d * NH;
    red_v4(sp, lrelu_exp(a0.x, b0.x), lrelu_exp(a0.y, b0.y),
               lrelu_exp(a0.z, b0.z), lrelu_exp(a0.w, b0.w));
    red_v4(sp + 4, lrelu_exp(a1.x, b1.x), lrelu_exp(a1.y, b1.y),
                   lrelu_exp(a1.z, b1.z), lrelu_exp(a1.w, b1.w));
}

// ---------------- K4b: invert denominators ---------------------------------
__global__ void k_sinv() {
    int i = blockIdx.x * blockDim.x + threadIdx.x;
    if (i < NN * NH) g_s[i] = __frcp_rn(g_s[i]);
}

// ---------------- K5: edge pass 2 — message scatter (4 threads/edge) -------
__global__ void k_edge_msg(const int* __restrict__ ei) {
    int gt = blockIdx.x * blockDim.x + threadIdx.x;
    int e = gt >> 2, q = gt & 3;
    if (e >= NE) return;
    int s = ei[e];
    int d = ei[NE + e];

    float2 as2 = *(const float2*)(g_asrc + s * NH + q * 2);
    float2 ad2 = *(const float2*)(g_adst + d * NH + q * 2);
    float2 si2 = *(const float2*)(g_s + d * NH + q * 2);
    float2 alq;
    alq.x = 0.125f * lrelu_exp(as2.x, ad2.x) * si2.x;
    alq.y = 0.125f * lrelu_exp(as2.y, ad2.y) * si2.y;

    unsigned long long v0 = *(unsigned long long*)&alq;
    unsigned long long v1 = __shfl_xor_sync(0xffffffffu, v0, 1);
    unsigned long long v2 = __shfl_xor_sync(0xffffffffu, v0, 2);
    unsigned long long v3 = __shfl_xor_sync(0xffffffffu, v1, 2);
    float2 p1 = *(float2*)&v1, p2 = *(float2*)&v2, p3 = *(float2*)&v3;

    float al[8];
#pragma unroll
    for (int i = 0; i < 4; ++i) {
        int r = i ^ q;
        float2 p = (r == 0) ? alq : (r == 1) ? p1 : (r == 2) ? p2 : p3;
        al[2 * i] = p.x;
        al[2 * i + 1] = p.y;
    }

    const __nv_bfloat16* hrow = g_hb + (size_t)s * NF + q * 4;
    float r0 = 0.f, r1 = 0.f, r2 = 0.f, r3 = 0.f;
#pragma unroll
    for (int h = 0; h < NH; ++h) {
        __nv_bfloat162 p01 = *(const __nv_bfloat162*)(hrow + h * 16);
        __nv_bfloat162 p23 = *(const __nv_bfloat162*)(hrow + h * 16 + 2);
        float2 f01 = __bfloat1622float2(p01);
        float2 f23 = __bfloat1622float2(p23);
        r0 = fmaf(al[h], f01.x, r0);
        r1 = fmaf(al[h], f01.y, r1);
        r2 = fmaf(al[h], f23.x, r2);
        r3 = fmaf(al[h], f23.y, r3);
    }
    red_v4(g_acc + d * NC + q * 4, r0, r1, r2, r3);
}

// ---------------- K6: node finalize (self-loop + bias + ELU + pool) --------
__global__ void k_node_final(const int* __restrict__ batch,
                             const float* __restrict__ bias) {
    int gt = blockIdx.x * blockDim.x + threadIdx.x;
    int n = gt >> 4, c = gt & 15;
    if (n >= NN) return;
    float v = g_acc[n * NC + c];
    const __nv_bfloat16* hr = g_hb + (size_t)n * NF;
#pragma unroll
    for (int h = 0; h < NH; ++h) {
        float a = g_asrc[n * NH + h] + g_adst[n * NH + h];
        a = a > 0.f ? a : 0.2f * a;
        float w = __expf(a) * g_s[n * NH + h];   // g_s holds 1/s
        v = fmaf(0.125f * w, __bfloat162float(hr[h * 16 + c]), v);
    }
    v += bias[c];
    v = v > 0.f ? v : expm1f(v);
    int b = batch[n];
    atomicAdd(&g_pool[b * NC + c], v);
    if (c == 0) atomicAdd(&g_cnt[b], 1.0f);
}

// ---------------- K7: pooled mean ------------------------------------------
__global__ void k_pool_div(float* __restrict__ out) {
    int i = blockIdx.x * blockDim.x + threadIdx.x;
    if (i < NG * NC) {
        int g = i >> 4;
        out[i] = g_pool[i] / fmaxf(g_cnt[g], 1.0f);
    }
}

// ---------------- launch ----------------------------------------------------
extern "C" void kernel_launch(void* const* d_in, const int* in_sizes, int n_in,
                              void* d_out, int out_size) {
    const float* x = (const float*)d_in[0];
    const int* ei = (const int*)d_in[1];
    const int* batch = (const int*)d_in[2];
    const float* gamma = (const float*)d_in[3];
    const float* beta = (const float*)d_in[4];
    const float* W = (const float*)d_in[5];
    const float* attS = (const float*)d_in[6];
    const float* attD = (const float*)d_in[7];
    const float* bias = (const float*)d_in[8];
    float* out = (float*)d_out;

    cudaFuncSetAttribute(k_gemm, cudaFuncAttributeMaxDynamicSharedMemorySize,
                         GEMM_SMEM_BYTES);

    k_zero<<<256, 256>>>();
    k_stats<<<512, 256>>>(x);
    k_bnfin<<<1, 128>>>(gamma, beta);
    k_prep<<<65, 256>>>(W);
    k_gemm<<<(NN + 127) / 128, 256, GEMM_SMEM_BYTES>>>(x, attS, attD);
    k_edge_s<<<(NE + 255) / 256, 256>>>(ei);
    k_sinv<<<(NN * NH + 255) / 256, 256>>>();
    k_edge_msg<<<(NE * 4 + 255) / 256, 256>>>(ei);
    k_node_final<<<(NN * 16 + 255) / 256, 256>>>(batch, bias);
    k_pool_div<<<(NG * NC + 255) / 256, 256>>>(out);
}

// round 12
// speedup vs baseline: 1.2638x; 1.0203x over previous
#include <cuda_runtime.h>
#include <cuda_bf16.h>
#include <math.h>

#define NN 100000
#define NE 1600000
#define NG 100
#define NH 8
#define NC 16
#define NF 128

// ---------------- scratch (static device globals) ---------------------------
__device__ __align__(16) __nv_bfloat16 g_hb[(size_t)NN * NF];  // 25.6 MB h (bf16)
__device__ __align__(16) float g_asrc[NN * NH];
__device__ __align__(16) float g_adst[NN * NH];
__device__ __align__(16) float g_s[NN * NH];           // softmax denom, then inverted
__device__ __align__(16) float g_pk[NN * 16];          // packed {adst pair, sinv pair} x4
__device__ __align__(16) float g_acc[NN * NC];         // head-averaged message accum
__device__ __align__(16) float g_colsum[NF];
__device__ __align__(16) float g_colsq[NF];
__device__ __align__(16) float g_scale[NF];
__device__ __align__(16) float g_shift[NF];
__device__ __align__(16) float g_Wp[NF * NF];          // BN-folded weights
__device__ __align__(16) float g_bp[NF];               // BN-folded bias
__device__ __align__(16) float g_pool[NG * NC];
__device__ __align__(16) float g_cnt[NG];

// vector reduction (no return) ----------------------------------------------
__device__ __forceinline__ void red_v4(float* p, float a, float b, float c, float d) {
    asm volatile("red.global.add.v4.f32 [%0], {%1, %2, %3, %4};"
                 :: "l"(p), "f"(a), "f"(b), "f"(c), "f"(d) : "memory");
}

__device__ __forceinline__ unsigned f2tf32(float f) {
    unsigned r;
    asm("cvt.rna.tf32.f32 %0, %1;" : "=r"(r) : "f"(f));
    return r;
}

// ---------------- K0: zero accumulators ------------------------------------
__global__ void k_zero() {
    int i = blockIdx.x * blockDim.x + threadIdx.x;
    int st = gridDim.x * blockDim.x;
    for (int k = i; k < NN * NC; k += st) g_acc[k] = 0.f;
    if (i < NF) { g_colsum[i] = 0.f; g_colsq[i] = 0.f; }
    if (i < NG * NC) g_pool[i] = 0.f;
    if (i < NG) g_cnt[i] = 0.f;
}

// ---------------- K1: BN column stats --------------------------------------
__global__ void k_stats(const float* __restrict__ x) {
    __shared__ float ssum[NF];
    __shared__ float ssq[NF];
    int t = threadIdx.x;
    int lane = t & 31;
    int warp = t >> 5;
    int col = lane * 4;
    if (t < NF) { ssum[t] = 0.f; ssq[t] = 0.f; }
    __syncthreads();

    float s0 = 0.f, s1 = 0.f, s2 = 0.f, s3 = 0.f;
    float q0 = 0.f, q1 = 0.f, q2 = 0.f, q3 = 0.f;
    int row = blockIdx.x * 8 + warp;
    int step = gridDim.x * 8;
    for (int r = row; r < NN; r += step) {
        float4 v = *(const float4*)(x + (size_t)r * NF + col);
        s0 += v.x; s1 += v.y; s2 += v.z; s3 += v.w;
        q0 += v.x * v.x; q1 += v.y * v.y; q2 += v.z * v.z; q3 += v.w * v.w;
    }
    atomicAdd(&ssum[col + 0], s0); atomicAdd(&ssum[col + 1], s1);
    atomicAdd(&ssum[col + 2], s2); atomicAdd(&ssum[col + 3], s3);
    atomicAdd(&ssq[col + 0], q0);  atomicAdd(&ssq[col + 1], q1);
    atomicAdd(&ssq[col + 2], q2);  atomicAdd(&ssq[col + 3], q3);
    __syncthreads();
    if (t < NF) {
        atomicAdd(&g_colsum[t], ssum[t]);
        atomicAdd(&g_colsq[t], ssq[t]);
    }
}

// ---------------- K2: finalize BN scale/shift ------------------------------
__global__ void k_bnfin(const float* __restrict__ gamma, const float* __restrict__ beta) {
    int t = threadIdx.x;
    if (t < NF) {
        float mean = g_colsum[t] * (1.f / NN);
        float var = g_colsq[t] * (1.f / NN) - mean * mean;
        float sc = gamma[t] * rsqrtf(var + 1e-5f);
        g_scale[t] = sc;
        g_shift[t] = beta[t] - mean * sc;
    }
}

// ---------------- K2b: fold BN into weights (bias: warp per column) --------
__global__ void k_prep(const float* __restrict__ W) {
    if (blockIdx.x < 64) {
        int i = blockIdx.x * 256 + threadIdx.x;
        int k = i >> 7;
        g_Wp[i] = g_scale[k] * W[i];
    } else {
        int j = (blockIdx.x - 64) * 8 + (threadIdx.x >> 5);  // column 0..127
        int lane = threadIdx.x & 31;
        float b = 0.f;
#pragma unroll
        for (int k = lane; k < NF; k += 32)
            b = fmaf(g_shift[k], W[k * NF + j], b);
        b += __shfl_xor_sync(0xffffffffu, b, 16);
        b += __shfl_xor_sync(0xffffffffu, b, 8);
        b += __shfl_xor_sync(0xffffffffu, b, 4);
        b += __shfl_xor_sync(0xffffffffu, b, 2);
        b += __shfl_xor_sync(0xffffffffu, b, 1);
        if (lane == 0) g_bp[j] = b;
    }
}

// ---------------- K3: tensor-core GEMM x@W' + b' + logits -------------------
#define XS_STRIDE 36
#define WS_STRIDE 136
#define XCHUNK_FLOATS (128 * XS_STRIDE)
#define WSM_FLOATS (NF * WS_STRIDE)
#define GEMM_SMEM_BYTES ((WSM_FLOATS + 2 * XCHUNK_FLOATS) * 4)

#define MMA_TF32(d, a, b)                                                     \
    asm volatile(                                                             \
        "mma.sync.aligned.m16n8k8.row.col.f32.tf32.tf32.f32 "                 \
        "{%0,%1,%2,%3}, {%4,%5,%6,%7}, {%8,%9}, {%0,%1,%2,%3};"               \
        : "+f"(d[0]), "+f"(d[1]), "+f"(d[2]), "+f"(d[3])                      \
        : "r"(a[0]), "r"(a[1]), "r"(a[2]), "r"(a[3]), "r"(b[0]), "r"(b[1]))

__device__ __forceinline__ void cp16(void* dst_smem, const void* src, int sz) {
    unsigned d = (unsigned)__cvta_generic_to_shared(dst_smem);
    asm volatile("cp.async.cg.shared.global [%0], [%1], 16, %2;"
                 :: "r"(d), "l"(src), "r"(sz));
}
#define CP_COMMIT() asm volatile("cp.async.commit_group;")

__global__ void __launch_bounds__(256, 2)
k_gemm(const float* __restrict__ x,
       const float* __restrict__ attS, const float* __restrict__ attD) {
    extern __shared__ float smem[];
    float* Wsm = smem;                       // [k][n] stride 136 (tf32 bits)
    float* Xs0 = smem + WSM_FLOATS;          // [row][k] stride 36, stage 0
    float* Xs1 = Xs0 + XCHUNK_FLOATS;        // stage 1

    int t = threadIdx.x;
    int lane = t & 31;
    int wid = t >> 5;
    int g = lane >> 2, tg = lane & 3;
    int wm = wid & 1, wn = wid >> 1;         // 2 x 4 warp grid
    int r0 = blockIdx.x * 128;

    // issue x chunk 0 (rows r0..r0+127, k 0..31)
#pragma unroll
    for (int p = 0; p < 4; ++p) {
        int idx = t + p * 256;
        int row = idx >> 3, grp = idx & 7;
        int n = r0 + row;
        cp16(Xs0 + row * XS_STRIDE + grp * 4,
             x + (size_t)n * NF + grp * 4, (n < NN) ? 16 : 0);
    }
    CP_COMMIT();

    // stage W' whole, rna-converted to tf32 at staging
#pragma unroll
    for (int p = 0; p < 16; ++p) {
        int i = t + p * 256;
        int row = i >> 5, grp = i & 31;
        float4 v = ((const float4*)(g_Wp + row * NF))[grp];
        unsigned* dst = (unsigned*)(Wsm + row * WS_STRIDE + grp * 4);
        dst[0] = f2tf32(v.x); dst[1] = f2tf32(v.y);
        dst[2] = f2tf32(v.z); dst[3] = f2tf32(v.w);
    }

    float acc[4][4][4];
#pragma unroll
    for (int i = 0; i < 4; ++i)
#pragma unroll
        for (int j = 0; j < 4; ++j)
#pragma unroll
            for (int c = 0; c < 4; ++c) acc[i][j][c] = 0.f;

#pragma unroll
    for (int kc = 0; kc < 4; ++kc) {
        if (kc < 3) {
            float* Xs = (kc & 1) ? Xs0 : Xs1;   // next buffer
            int kbase = (kc + 1) * 32;
#pragma unroll
            for (int p = 0; p < 4; ++p) {
                int idx = t + p * 256;
                int row = idx >> 3, grp = idx & 7;
                int n = r0 + row;
                cp16(Xs + row * XS_STRIDE + grp * 4,
                     x + (size_t)n * NF + kbase + grp * 4, (n < NN) ? 16 : 0);
            }
            CP_COMMIT();
            asm volatile("cp.async.wait_group 1;");
        } else {
            asm volatile("cp.async.wait_group 0;");
        }
        __syncthreads();

        // in-place rna conversion of this chunk (16 elts/thread)
        float* Xsf = (kc & 1) ? Xs1 : Xs0;
        unsigned* Xsu = (unsigned*)Xsf;
#pragma unroll
        for (int p = 0; p < 16; ++p) {
            int idx = t + p * 256;
            int row = idx >> 5, col = idx & 31;
            int a = row * XS_STRIDE + col;
            Xsu[a] = f2tf32(Xsf[a]);
        }
        __syncthreads();

        const unsigned* Xs = Xsu;
#pragma unroll
        for (int ks = 0; ks < 4; ++ks) {
            int k = ks * 8;
            unsigned a[4][4], b[4][2];
#pragma unroll
            for (int i = 0; i < 4; ++i) {
                int rlo = wm * 64 + i * 16 + g;
                a[i][0] = Xs[rlo * XS_STRIDE + k + tg];
                a[i][1] = Xs[(rlo + 8) * XS_STRIDE + k + tg];
                a[i][2] = Xs[rlo * XS_STRIDE + k + tg + 4];
                a[i][3] = Xs[(rlo + 8) * XS_STRIDE + k + tg + 4];
            }
#pragma unroll
            for (int j = 0; j < 4; ++j) {
                int c = wn * 32 + j * 8 + g;
                b[j][0] = __float_as_uint(Wsm[(kc * 32 + k + tg) * WS_STRIDE + c]);
                b[j][1] = __float_as_uint(Wsm[(kc * 32 + k + tg + 4) * WS_STRIDE + c]);
            }
#pragma unroll
            for (int i = 0; i < 4; ++i)
#pragma unroll
                for (int j = 0; j < 4; ++j) MMA_TF32(acc[i][j], a[i], b[j]);
        }
        __syncthreads();
    }

    int rowsValid = NN - r0;
    if (rowsValid > 128) rowsValid = 128;

    // add folded-BN bias b'[col]
#pragma unroll
    for (int j = 0; j < 4; ++j) {
        int c0 = wn * 32 + j * 8 + 2 * tg;
        float b0 = g_bp[c0], b1 = g_bp[c0 + 1];
#pragma unroll
        for (int i = 0; i < 4; ++i) {
            acc[i][j][0] += b0; acc[i][j][1] += b1;
            acc[i][j][2] += b0; acc[i][j][3] += b1;
        }
    }

    // store h tile as bf16 from fragments
#pragma unroll
    for (int i = 0; i < 4; ++i) {
        int rlo = wm * 64 + i * 16 + g;
        int rhi = rlo + 8;
#pragma unroll
        for (int j = 0; j < 4; ++j) {
            int c0 = wn * 32 + j * 8 + 2 * tg;
            if (rlo < rowsValid) {
                __nv_bfloat162 p = __float22bfloat162_rn(
                    make_float2(acc[i][j][0], acc[i][j][1]));
                *(__nv_bfloat162*)(g_hb + (size_t)(r0 + rlo) * NF + c0) = p;
            }
            if (rhi < rowsValid) {
                __nv_bfloat162 p = __float22bfloat162_rn(
                    make_float2(acc[i][j][2], acc[i][j][3]));
                *(__nv_bfloat162*)(g_hb + (size_t)(r0 + rhi) * NF + c0) = p;
            }
        }
    }

    // attention logits: warp covers heads {2wn, 2wn+1}; quad-reduce over tg
    float aS[2][2][2], aD[2][2][2];
#pragma unroll
    for (int hl = 0; hl < 2; ++hl)
#pragma unroll
        for (int j2 = 0; j2 < 2; ++j2) {
            int base = (2 * wn + hl) * 16 + j2 * 8 + 2 * tg;
            aS[hl][j2][0] = attS[base];     aS[hl][j2][1] = attS[base + 1];
            aD[hl][j2][0] = attD[base];     aD[hl][j2][1] = attD[base + 1];
        }

#pragma unroll
    for (int i = 0; i < 4; ++i) {
#pragma unroll
        for (int hl = 0; hl < 2; ++hl) {
            float psl = 0.f, pdl = 0.f, psh = 0.f, pdh = 0.f;
#pragma unroll
            for (int j2 = 0; j2 < 2; ++j2) {
                int j = 2 * hl + j2;
                psl = fmaf(acc[i][j][0], aS[hl][j2][0],
                      fmaf(acc[i][j][1], aS[hl][j2][1], psl));
                pdl = fmaf(acc[i][j][0], aD[hl][j2][0],
                      fmaf(acc[i][j][1], aD[hl][j2][1], pdl));
                psh = fmaf(acc[i][j][2], aS[hl][j2][0],
                      fmaf(acc[i][j][3], aS[hl][j2][1], psh));
                pdh = fmaf(acc[i][j][2], aD[hl][j2][0],
                      fmaf(acc[i][j][3], aD[hl][j2][1], pdh));
            }
            psl += __shfl_xor_sync(0xffffffffu, psl, 1);
            psl += __shfl_xor_sync(0xffffffffu, psl, 2);
            pdl += __shfl_xor_sync(0xffffffffu, pdl, 1);
            pdl += __shfl_xor_sync(0xffffffffu, pdl, 2);
            psh += __shfl_xor_sync(0xffffffffu, psh, 1);
            psh += __shfl_xor_sync(0xffffffffu, psh, 2);
            pdh += __shfl_xor_sync(0xffffffffu, pdh, 1);
            pdh += __shfl_xor_sync(0xffffffffu, pdh, 2);
            if (tg == 0) {
                int h = 2 * wn + hl;
                int rlo = wm * 64 + i * 16 + g;
                int rhi = rlo + 8;
                if (rlo < rowsValid) {
                    int n = r0 + rlo;
                    g_asrc[n * NH + h] = psl;
                    g_adst[n * NH + h] = pdl;
                    float e = psl + pdl;
                    e = e > 0.f ? e : 0.2f * e;
                    g_s[n * NH + h] = __expf(e);
                }
                if (rhi < rowsValid) {
                    int n = r0 + rhi;
                    g_asrc[n * NH + h] = psh;
                    g_adst[n * NH + h] = pdh;
                    float e = psh + pdh;
                    e = e > 0.f ? e : 0.2f * e;
                    g_s[n * NH + h] = __expf(e);
                }
            }
        }
    }
}

// ---------------- K4: edge pass 1 — softmax denominators -------------------
__device__ __forceinline__ float lrelu_exp(float a, float b) {
    float e = a + b;
    e = e > 0.f ? e : 0.2f * e;
    return __expf(e);
}

__global__ void k_edge_s(const int* __restrict__ ei) {
    int e = blockIdx.x * blockDim.x + threadIdx.x;
    if (e >= NE) return;
    int s = ei[e];
    int d = ei[NE + e];
    float4 a0 = *(const float4*)(g_asrc + s * NH);
    float4 a1 = *(const float4*)(g_asrc + s * NH + 4);
    float4 b0 = *(const float4*)(g_adst + d * NH);
    float4 b1 = *(const float4*)(g_adst + d * NH + 4);
    float* sp = g_s + d * NH;
    red_v4(sp, lrelu_exp(a0.x, b0.x), lrelu_exp(a0.y, b0.y),
               lrelu_exp(a0.z, b0.z), lrelu_exp(a0.w, b0.w));
    red_v4(sp + 4, lrelu_exp(a1.x, b1.x), lrelu_exp(a1.y, b1.y),
                   lrelu_exp(a1.z, b1.z), lrelu_exp(a1.w, b1.w));
}

// ---------------- K4b: invert denominators + build packed dst rows ---------
__global__ void k_sinv() {
    int i = blockIdx.x * blockDim.x + threadIdx.x;
    if (i >= NN * 4) return;
    int n = i >> 2, q = i & 3;
    float2 ad = *(const float2*)(g_adst + n * NH + q * 2);
    float2 sv = *(const float2*)(g_s + n * NH + q * 2);
    float i0 = __frcp_rn(sv.x), i1 = __frcp_rn(sv.y);
    *(float2*)(g_s + n * NH + q * 2) = make_float2(i0, i1);
    *(float4*)(g_pk + n * 16 + q * 4) = make_float4(ad.x, ad.y, i0, i1);
}

// ---------------- K5: edge pass 2 — message scatter (4 threads/edge) -------
// Thread q: asrc pair gather (8B) + packed dst float4 gather (16B).
__global__ void k_edge_msg(const int* __restrict__ ei) {
    int gt = blockIdx.x * blockDim.x + threadIdx.x;
    int e = gt >> 2, q = gt & 3;
    if (e >= NE) return;
    int s = ei[e];
    int d = ei[NE + e];

    float2 as2 = *(const float2*)(g_asrc + s * NH + q * 2);
    float4 pk = *(const float4*)(g_pk + d * 16 + q * 4);  // {adst2q, adst2q+1, sinv2q, sinv2q+1}
    float2 alq;
    alq.x = 0.125f * lrelu_exp(as2.x, pk.x) * pk.z;
    alq.y = 0.125f * lrelu_exp(as2.y, pk.y) * pk.w;

    unsigned long long v0 = *(unsigned long long*)&alq;
    unsigned long long v1 = __shfl_xor_sync(0xffffffffu, v0, 1);
    unsigned long long v2 = __shfl_xor_sync(0xffffffffu, v0, 2);
    unsigned long long v3 = __shfl_xor_sync(0xffffffffu, v1, 2);
    float2 p1 = *(float2*)&v1, p2 = *(float2*)&v2, p3 = *(float2*)&v3;

    float al[8];
#pragma unroll
    for (int i = 0; i < 4; ++i) {
        int r = i ^ q;
        float2 p = (r == 0) ? alq : (r == 1) ? p1 : (r == 2) ? p2 : p3;
        al[2 * i] = p.x;
        al[2 * i + 1] = p.y;
    }

    const __nv_bfloat16* hrow = g_hb + (size_t)s * NF + q * 4;
    float r0 = 0.f, r1 = 0.f, r2 = 0.f, r3 = 0.f;
#pragma unroll
    for (int h = 0; h < NH; ++h) {
        __nv_bfloat162 p01 = *(const __nv_bfloat162*)(hrow + h * 16);
        __nv_bfloat162 p23 = *(const __nv_bfloat162*)(hrow + h * 16 + 2);
        float2 f01 = __bfloat1622float2(p01);
        float2 f23 = __bfloat1622float2(p23);
        r0 = fmaf(al[h], f01.x, r0);
        r1 = fmaf(al[h], f01.y, r1);
        r2 = fmaf(al[h], f23.x, r2);
        r3 = fmaf(al[h], f23.y, r3);
    }
    red_v4(g_acc + d * NC + q * 4, r0, r1, r2, r3);
}

// ---------------- K6: node finalize (self-loop + bias + ELU + pool) --------
__global__ void k_node_final(const int* __restrict__ batch,
                             const float* __restrict__ bias) {
    int gt = blockIdx.x * blockDim.x + threadIdx.x;
    int n = gt >> 4, c = gt & 15;
    if (n >= NN) return;
    float v = g_acc[n * NC + c];
    const __nv_bfloat16* hr = g_hb + (size_t)n * NF;
#pragma unroll
    for (int h = 0; h < NH; ++h) {
        float a = g_asrc[n * NH + h] + g_adst[n * NH + h];
        a = a > 0.f ? a : 0.2f * a;
        float w = __expf(a) * g_s[n * NH + h];   // g_s holds 1/s
        v = fmaf(0.125f * w, __bfloat162float(hr[h * 16 + c]), v);
    }
    v += bias[c];
    v = v > 0.f ? v : expm1f(v);
    int b = batch[n];
    atomicAdd(&g_pool[b * NC + c], v);
    if (c == 0) atomicAdd(&g_cnt[b], 1.0f);
}

// ---------------- K7: pooled mean ------------------------------------------
__global__ void k_pool_div(float* __restrict__ out) {
    int i = blockIdx.x * blockDim.x + threadIdx.x;
    if (i < NG * NC) {
        int g = i >> 4;
        out[i] = g_pool[i] / fmaxf(g_cnt[g], 1.0f);
    }
}

// ---------------- launch ----------------------------------------------------
extern "C" void kernel_launch(void* const* d_in, const int* in_sizes, int n_in,
                              void* d_out, int out_size) {
    const float* x = (const float*)d_in[0];
    const int* ei = (const int*)d_in[1];
    const int* batch = (const int*)d_in[2];
    const float* gamma = (const float*)d_in[3];
    const float* beta = (const float*)d_in[4];
    const float* W = (const float*)d_in[5];
    const float* attS = (const float*)d_in[6];
    const float* attD = (const float*)d_in[7];
    const float* bias = (const float*)d_in[8];
    float* out = (float*)d_out;

    cudaFuncSetAttribute(k_gemm, cudaFuncAttributeMaxDynamicSharedMemorySize,
                         GEMM_SMEM_BYTES);

    k_zero<<<256, 256>>>();
    k_stats<<<512, 256>>>(x);
    k_bnfin<<<1, 128>>>(gamma, beta);
    k_prep<<<80, 256>>>(W);
    k_gemm<<<(NN + 127) / 128, 256, GEMM_SMEM_BYTES>>>(x, attS, attD);
    k_edge_s<<<(NE + 255) / 256, 256>>>(ei);
    k_sinv<<<(NN * 4 + 255) / 256, 256>>>();
    k_edge_msg<<<(NE * 4 + 255) / 256, 256>>>(ei);
    k_node_final<<<(NN * 16 + 255) / 256, 256>>>(batch, bias);
    k_pool_div<<<(NG * NC + 255) / 256, 256>>>(out);
}

// round 13
// speedup vs baseline: 1.2684x; 1.0037x over previous
#include <cuda_runtime.h>
#include <cuda_bf16.h>
#include <math.h>

#define NN 100000
#define NE 1600000
#define NG 100
#define NH 8
#define NC 16
#define NF 128

// ---------------- scratch (static device globals) ---------------------------
__device__ __align__(16) __nv_bfloat16 g_hb[(size_t)NN * NF];  // 25.6 MB h (bf16)
__device__ __align__(16) float g_asrc[NN * NH];
__device__ __align__(16) float g_adst[NN * NH];
__device__ __align__(16) float g_s[NN * NH];           // softmax denom, then inverted
__device__ __align__(16) float g_pk[NN * 16];          // packed {adst pair, sinv pair} x4
__device__ __align__(16) float g_acc[NN * NC];         // head-averaged message accum
__device__ __align__(16) float g_colsum[NF];
__device__ __align__(16) float g_colsq[NF];
__device__ __align__(16) float g_Wp[NF * NF];          // BN-folded weights
__device__ __align__(16) float g_bp[NF];               // BN-folded bias
__device__ __align__(16) float g_pool[NG * NC];
__device__ __align__(16) float g_cnt[NG];

// vector reduction (no return) ----------------------------------------------
__device__ __forceinline__ void red_v4(float* p, float a, float b, float c, float d) {
    asm volatile("red.global.add.v4.f32 [%0], {%1, %2, %3, %4};"
                 :: "l"(p), "f"(a), "f"(b), "f"(c), "f"(d) : "memory");
}

__device__ __forceinline__ unsigned f2tf32(float f) {
    unsigned r;
    asm("cvt.rna.tf32.f32 %0, %1;" : "=r"(r) : "f"(f));
    return r;
}

__device__ __forceinline__ void bn_coeff(int k, const float* gamma, const float* beta,
                                         float& sc, float& sh) {
    float mean = g_colsum[k] * (1.f / NN);
    float var = g_colsq[k] * (1.f / NN) - mean * mean;
    sc = gamma[k] * rsqrtf(var + 1e-5f);
    sh = beta[k] - mean * sc;
}

// ---------------- K1: BN column stats + zero accumulators -------------------
__global__ void k_stats(const float* __restrict__ x) {
    __shared__ float ssum[NF];
    __shared__ float ssq[NF];
    int t = threadIdx.x;
    int lane = t & 31;
    int warp = t >> 5;
    int col = lane * 4;
    if (t < NF) { ssum[t] = 0.f; ssq[t] = 0.f; }
    if (blockIdx.x == 0 && t == 0) {
        // colsum/colsq must be zero before block atomics; done host-free via
        // a dedicated first-block race-free path is unsafe -> instead zero
        // them with fixed values below (atomic adds start from whatever is
        // here). We zero them in k_stats grid-stride BEFORE any atomics via
        // the separate loop + a gridwide assumption is NOT safe either.
    }
    __syncthreads();

    // zero accumulators (grid-stride over this kernel's 512 blocks)
    int gi = blockIdx.x * blockDim.x + t;
    int gst = gridDim.x * blockDim.x;
    for (int k = gi; k < NN * NC; k += gst) g_acc[k] = 0.f;
    if (gi < NG * NC) g_pool[gi] = 0.f;
    if (gi < NG) g_cnt[gi] = 0.f;
    if (gi < NF) { g_colsum[gi] = 0.f; g_colsq[gi] = 0.f; }
    // NOTE: colsum zeroing must be visible before ANY block's final atomics.
    // Safe because every block zeroes into smem first, accumulates locally,
    // and only block 0's gi<NF threads touch g_colsum before atomics — but
    // other blocks may finish earlier. To be strictly safe we instead have
    // ALL blocks atomically add into buffers that k_launch pre-poisons...
    // Simplest safe scheme: g_colsum/g_colsq are zeroed here ONLY by the
    // thread that also later atomically adds (no cross-block order needed
    // because zeroing happens before any atomicAdd in program order of the
    // SAME kernel only for block 0). -> use device-side first-touch flag-free
    // approach: since benchmark replays the graph, buffers persist. We make
    // the atomics self-initializing by having block 0 store and all blocks
    // atomicAdd AFTER a gridwide sync we don't have...
    // => Fall back: zero colsum/colsq at the END of the PREVIOUS launch is
    // not available; keep correctness by computing block-local sums and
    // using atomicExch-free protocol below.

    float s0 = 0.f, s1 = 0.f, s2 = 0.f, s3 = 0.f;
    float q0 = 0.f, q1 = 0.f, q2 = 0.f, q3 = 0.f;
    int row = blockIdx.x * 8 + warp;
    int step = gridDim.x * 8;
    for (int r = row; r < NN; r += step) {
        float4 v = *(const float4*)(x + (size_t)r * NF + col);
        s0 += v.x; s1 += v.y; s2 += v.z; s3 += v.w;
        q0 += v.x * v.x; q1 += v.y * v.y; q2 += v.z * v.z; q3 += v.w * v.w;
    }
    atomicAdd(&ssum[col + 0], s0); atomicAdd(&ssum[col + 1], s1);
    atomicAdd(&ssum[col + 2], s2); atomicAdd(&ssum[col + 3], s3);
    atomicAdd(&ssq[col + 0], q0);  atomicAdd(&ssq[col + 1], q1);
    atomicAdd(&ssq[col + 2], q2);  atomicAdd(&ssq[col + 3], q3);
    __syncthreads();
    if (t < NF) {
        atomicAdd(&g_colsum[t], ssum[t]);
        atomicAdd(&g_colsq[t], ssq[t]);
    }
}

// ---------------- K0b: zero colsum/colsq (must precede k_stats) -------------
__global__ void k_zero_stats() {
    int i = threadIdx.x;
    if (i < NF) { g_colsum[i] = 0.f; g_colsq[i] = 0.f; }
}

// ---------------- K2b: fold BN into weights (BN coeffs computed inline) -----
__global__ void k_prep(const float* __restrict__ W,
                       const float* __restrict__ gamma,
                       const float* __restrict__ beta) {
    if (blockIdx.x < 64) {
        __shared__ float ssc[2];
        int k0 = blockIdx.x * 2;
        if (threadIdx.x < 2) {
            float sc, sh;
            bn_coeff(k0 + threadIdx.x, gamma, beta, sc, sh);
            ssc[threadIdx.x] = sc;
        }
        __syncthreads();
        int i = blockIdx.x * 256 + threadIdx.x;
        int k = (i >> 7) - k0;
        g_Wp[i] = ssc[k] * W[i];
    } else {
        __shared__ float ssh[NF];
        if (threadIdx.x < NF) {
            float sc, sh;
            bn_coeff(threadIdx.x, gamma, beta, sc, sh);
            ssh[threadIdx.x] = sh;
        }
        __syncthreads();
        int j = (blockIdx.x - 64) * 8 + (threadIdx.x >> 5);  // column 0..127
        int lane = threadIdx.x & 31;
        float b = 0.f;
#pragma unroll
        for (int k = lane; k < NF; k += 32)
            b = fmaf(ssh[k], W[k * NF + j], b);
        b += __shfl_xor_sync(0xffffffffu, b, 16);
        b += __shfl_xor_sync(0xffffffffu, b, 8);
        b += __shfl_xor_sync(0xffffffffu, b, 4);
        b += __shfl_xor_sync(0xffffffffu, b, 2);
        b += __shfl_xor_sync(0xffffffffu, b, 1);
        if (lane == 0) g_bp[j] = b;
    }
}

// ---------------- K3: tensor-core GEMM x@W' + b' + logits -------------------
#define XS_STRIDE 36
#define WS_STRIDE 136
#define XCHUNK_FLOATS (128 * XS_STRIDE)
#define WSM_FLOATS (NF * WS_STRIDE)
#define GEMM_SMEM_BYTES ((WSM_FLOATS + 2 * XCHUNK_FLOATS) * 4)

#define MMA_TF32(d, a, b)                                                     \
    asm volatile(                                                             \
        "mma.sync.aligned.m16n8k8.row.col.f32.tf32.tf32.f32 "                 \
        "{%0,%1,%2,%3}, {%4,%5,%6,%7}, {%8,%9}, {%0,%1,%2,%3};"               \
        : "+f"(d[0]), "+f"(d[1]), "+f"(d[2]), "+f"(d[3])                      \
        : "r"(a[0]), "r"(a[1]), "r"(a[2]), "r"(a[3]), "r"(b[0]), "r"(b[1]))

__device__ __forceinline__ void cp16(void* dst_smem, const void* src, int sz) {
    unsigned d = (unsigned)__cvta_generic_to_shared(dst_smem);
    asm volatile("cp.async.cg.shared.global [%0], [%1], 16, %2;"
                 :: "r"(d), "l"(src), "r"(sz));
}
#define CP_COMMIT() asm volatile("cp.async.commit_group;")

__global__ void __launch_bounds__(256, 2)
k_gemm(const float* __restrict__ x,
       const float* __restrict__ attS, const float* __restrict__ attD) {
    extern __shared__ float smem[];
    float* Wsm = smem;                       // [k][n] stride 136 (tf32 bits)
    float* Xs0 = smem + WSM_FLOATS;          // [row][k] stride 36, stage 0
    float* Xs1 = Xs0 + XCHUNK_FLOATS;        // stage 1

    int t = threadIdx.x;
    int lane = t & 31;
    int wid = t >> 5;
    int g = lane >> 2, tg = lane & 3;
    int wm = wid & 1, wn = wid >> 1;         // 2 x 4 warp grid
    int r0 = blockIdx.x * 128;

    // issue x chunk 0 (rows r0..r0+127, k 0..31)
#pragma unroll
    for (int p = 0; p < 4; ++p) {
        int idx = t + p * 256;
        int row = idx >> 3, grp = idx & 7;
        int n = r0 + row;
        cp16(Xs0 + row * XS_STRIDE + grp * 4,
             x + (size_t)n * NF + grp * 4, (n < NN) ? 16 : 0);
    }
    CP_COMMIT();

    // stage W' whole, rna-converted to tf32 at staging
#pragma unroll
    for (int p = 0; p < 16; ++p) {
        int i = t + p * 256;
        int row = i >> 5, grp = i & 31;
        float4 v = ((const float4*)(g_Wp + row * NF))[grp];
        unsigned* dst = (unsigned*)(Wsm + row * WS_STRIDE + grp * 4);
        dst[0] = f2tf32(v.x); dst[1] = f2tf32(v.y);
        dst[2] = f2tf32(v.z); dst[3] = f2tf32(v.w);
    }

    float acc[4][4][4];
#pragma unroll
    for (int i = 0; i < 4; ++i)
#pragma unroll
        for (int j = 0; j < 4; ++j)
#pragma unroll
            for (int c = 0; c < 4; ++c) acc[i][j][c] = 0.f;

#pragma unroll
    for (int kc = 0; kc < 4; ++kc) {
        if (kc < 3) {
            float* Xs = (kc & 1) ? Xs0 : Xs1;   // next buffer
            int kbase = (kc + 1) * 32;
#pragma unroll
            for (int p = 0; p < 4; ++p) {
                int idx = t + p * 256;
                int row = idx >> 3, grp = idx & 7;
                int n = r0 + row;
                cp16(Xs + row * XS_STRIDE + grp * 4,
                     x + (size_t)n * NF + kbase + grp * 4, (n < NN) ? 16 : 0);
            }
            CP_COMMIT();
            asm volatile("cp.async.wait_group 1;");
        } else {
            asm volatile("cp.async.wait_group 0;");
        }
        __syncthreads();

        // in-place rna conversion of this chunk (16 elts/thread)
        float* Xsf = (kc & 1) ? Xs1 : Xs0;
        unsigned* Xsu = (unsigned*)Xsf;
#pragma unroll
        for (int p = 0; p < 16; ++p) {
            int idx = t + p * 256;
            int row = idx >> 5, col = idx & 31;
            int a = row * XS_STRIDE + col;
            Xsu[a] = f2tf32(Xsf[a]);
        }
        __syncthreads();

        const unsigned* Xs = Xsu;
#pragma unroll
        for (int ks = 0; ks < 4; ++ks) {
            int k = ks * 8;
            unsigned a[4][4], b[4][2];
#pragma unroll
            for (int i = 0; i < 4; ++i) {
                int rlo = wm * 64 + i * 16 + g;
                a[i][0] = Xs[rlo * XS_STRIDE + k + tg];
                a[i][1] = Xs[(rlo + 8) * XS_STRIDE + k + tg];
                a[i][2] = Xs[rlo * XS_STRIDE + k + tg + 4];
                a[i][3] = Xs[(rlo + 8) * XS_STRIDE + k + tg + 4];
            }
#pragma unroll
            for (int j = 0; j < 4; ++j) {
                int c = wn * 32 + j * 8 + g;
                b[j][0] = __float_as_uint(Wsm[(kc * 32 + k + tg) * WS_STRIDE + c]);
                b[j][1] = __float_as_uint(Wsm[(kc * 32 + k + tg + 4) * WS_STRIDE + c]);
            }
#pragma unroll
            for (int i = 0; i < 4; ++i)
#pragma unroll
                for (int j = 0; j < 4; ++j) MMA_TF32(acc[i][j], a[i], b[j]);
        }
        __syncthreads();
    }

    int rowsValid = NN - r0;
    if (rowsValid > 128) rowsValid = 128;

    // add folded-BN bias b'[col]
#pragma unroll
    for (int j = 0; j < 4; ++j) {
        int c0 = wn * 32 + j * 8 + 2 * tg;
        float b0 = g_bp[c0], b1 = g_bp[c0 + 1];
#pragma unroll
        for (int i = 0; i < 4; ++i) {
            acc[i][j][0] += b0; acc[i][j][1] += b1;
            acc[i][j][2] += b0; acc[i][j][3] += b1;
        }
    }

    // store h tile as bf16 from fragments
#pragma unroll
    for (int i = 0; i < 4; ++i) {
        int rlo = wm * 64 + i * 16 + g;
        int rhi = rlo + 8;
#pragma unroll
        for (int j = 0; j < 4; ++j) {
            int c0 = wn * 32 + j * 8 + 2 * tg;
            if (rlo < rowsValid) {
                __nv_bfloat162 p = __float22bfloat162_rn(
                    make_float2(acc[i][j][0], acc[i][j][1]));
                *(__nv_bfloat162*)(g_hb + (size_t)(r0 + rlo) * NF + c0) = p;
            }
            if (rhi < rowsValid) {
                __nv_bfloat162 p = __float22bfloat162_rn(
                    make_float2(acc[i][j][2], acc[i][j][3]));
                *(__nv_bfloat162*)(g_hb + (size_t)(r0 + rhi) * NF + c0) = p;
            }
        }
    }

    // attention logits: warp covers heads {2wn, 2wn+1}; quad-reduce over tg
    float aS[2][2][2], aD[2][2][2];
#pragma unroll
    for (int hl = 0; hl < 2; ++hl)
#pragma unroll
        for (int j2 = 0; j2 < 2; ++j2) {
            int base = (2 * wn + hl) * 16 + j2 * 8 + 2 * tg;
            aS[hl][j2][0] = attS[base];     aS[hl][j2][1] = attS[base + 1];
            aD[hl][j2][0] = attD[base];     aD[hl][j2][1] = attD[base + 1];
        }

#pragma unroll
    for (int i = 0; i < 4; ++i) {
#pragma unroll
        for (int hl = 0; hl < 2; ++hl) {
            float psl = 0.f, pdl = 0.f, psh = 0.f, pdh = 0.f;
#pragma unroll
            for (int j2 = 0; j2 < 2; ++j2) {
                int j = 2 * hl + j2;
                psl = fmaf(acc[i][j][0], aS[hl][j2][0],
                      fmaf(acc[i][j][1], aS[hl][j2][1], psl));
                pdl = fmaf(acc[i][j][0], aD[hl][j2][0],
                      fmaf(acc[i][j][1], aD[hl][j2][1], pdl));
                psh = fmaf(acc[i][j][2], aS[hl][j2][0],
                      fmaf(acc[i][j][3], aS[hl][j2][1], psh));
                pdh = fmaf(acc[i][j][2], aD[hl][j2][0],
                      fmaf(acc[i][j][3], aD[hl][j2][1], pdh));
            }
            psl += __shfl_xor_sync(0xffffffffu, psl, 1);
            psl += __shfl_xor_sync(0xffffffffu, psl, 2);
            pdl += __shfl_xor_sync(0xffffffffu, pdl, 1);
            pdl += __shfl_xor_sync(0xffffffffu, pdl, 2);
            psh += __shfl_xor_sync(0xffffffffu, psh, 1);
            psh += __shfl_xor_sync(0xffffffffu, psh, 2);
            pdh += __shfl_xor_sync(0xffffffffu, pdh, 1);
            pdh += __shfl_xor_sync(0xffffffffu, pdh, 2);
            if (tg == 0) {
                int h = 2 * wn + hl;
                int rlo = wm * 64 + i * 16 + g;
                int rhi = rlo + 8;
                if (rlo < rowsValid) {
                    int n = r0 + rlo;
                    g_asrc[n * NH + h] = psl;
                    g_adst[n * NH + h] = pdl;
                    float e = psl + pdl;
                    e = e > 0.f ? e : 0.2f * e;
                    g_s[n * NH + h] = __expf(e);
                }
                if (rhi < rowsValid) {
                    int n = r0 + rhi;
                    g_asrc[n * NH + h] = psh;
                    g_adst[n * NH + h] = pdh;
                    float e = psh + pdh;
                    e = e > 0.f ? e : 0.2f * e;
                    g_s[n * NH + h] = __expf(e);
                }
            }
        }
    }
}

// ---------------- K4: edge pass 1 — softmax denominators -------------------
__device__ __forceinline__ float lrelu_exp(float a, float b) {
    float e = a + b;
    e = e > 0.f ? e : 0.2f * e;
    return __expf(e);
}

__global__ void k_edge_s(const int* __restrict__ ei) {
    int e = blockIdx.x * blockDim.x + threadIdx.x;
    if (e >= NE) return;
    int s = ei[e];
    int d = ei[NE + e];
    float4 a0 = *(const float4*)(g_asrc + s * NH);
    float4 a1 = *(const float4*)(g_asrc + s * NH + 4);
    float4 b0 = *(const float4*)(g_adst + d * NH);
    float4 b1 = *(const float4*)(g_adst + d * NH + 4);
    float* sp = g_s + d * NH;
    red_v4(sp, lrelu_exp(a0.x, b0.x), lrelu_exp(a0.y, b0.y),
               lrelu_exp(a0.z, b0.z), lrelu_exp(a0.w, b0.w));
    red_v4(sp + 4, lrelu_exp(a1.x, b1.x), lrelu_exp(a1.y, b1.y),
                   lrelu_exp(a1.z, b1.z), lrelu_exp(a1.w, b1.w));
}

// ---------------- K4b: invert denominators + build packed dst rows ---------
__global__ void k_sinv() {
    int i = blockIdx.x * blockDim.x + threadIdx.x;
    if (i >= NN * 4) return;
    int n = i >> 2, q = i & 3;
    float2 ad = *(const float2*)(g_adst + n * NH + q * 2);
    float2 sv = *(const float2*)(g_s + n * NH + q * 2);
    float i0 = __frcp_rn(sv.x), i1 = __frcp_rn(sv.y);
    *(float2*)(g_s + n * NH + q * 2) = make_float2(i0, i1);
    *(float4*)(g_pk + n * 16 + q * 4) = make_float4(ad.x, ad.y, i0, i1);
}

// ---------------- K5: edge pass 2 — message scatter (4 threads/edge) -------
__global__ void k_edge_msg(const int* __restrict__ ei) {
    int gt = blockIdx.x * blockDim.x + threadIdx.x;
    int e = gt >> 2, q = gt & 3;
    if (e >= NE) return;
    int s = ei[e];
    int d = ei[NE + e];

    float2 as2 = *(const float2*)(g_asrc + s * NH + q * 2);
    float4 pk = *(const float4*)(g_pk + d * 16 + q * 4);
    float2 alq;
    alq.x = 0.125f * lrelu_exp(as2.x, pk.x) * pk.z;
    alq.y = 0.125f * lrelu_exp(as2.y, pk.y) * pk.w;

    unsigned long long v0 = *(unsigned long long*)&alq;
    unsigned long long v1 = __shfl_xor_sync(0xffffffffu, v0, 1);
    unsigned long long v2 = __shfl_xor_sync(0xffffffffu, v0, 2);
    unsigned long long v3 = __shfl_xor_sync(0xffffffffu, v1, 2);
    float2 p1 = *(float2*)&v1, p2 = *(float2*)&v2, p3 = *(float2*)&v3;

    float al[8];
#pragma unroll
    for (int i = 0; i < 4; ++i) {
        int r = i ^ q;
        float2 p = (r == 0) ? alq : (r == 1) ? p1 : (r == 2) ? p2 : p3;
        al[2 * i] = p.x;
        al[2 * i + 1] = p.y;
    }

    const __nv_bfloat16* hrow = g_hb + (size_t)s * NF + q * 4;
    float r0 = 0.f, r1 = 0.f, r2 = 0.f, r3 = 0.f;
#pragma unroll
    for (int h = 0; h < NH; ++h) {
        __nv_bfloat162 p01 = *(const __nv_bfloat162*)(hrow + h * 16);
        __nv_bfloat162 p23 = *(const __nv_bfloat162*)(hrow + h * 16 + 2);
        float2 f01 = __bfloat1622float2(p01);
        float2 f23 = __bfloat1622float2(p23);
        r0 = fmaf(al[h], f01.x, r0);
        r1 = fmaf(al[h], f01.y, r1);
        r2 = fmaf(al[h], f23.x, r2);
        r3 = fmaf(al[h], f23.y, r3);
    }
    red_v4(g_acc + d * NC + q * 4, r0, r1, r2, r3);
}

// ---------------- K6: node finalize (self-loop + bias + ELU + pool) --------
__global__ void k_node_final(const int* __restrict__ batch,
                             const float* __restrict__ bias) {
    int gt = blockIdx.x * blockDim.x + threadIdx.x;
    int n = gt >> 4, c = gt & 15;
    if (n >= NN) return;
    float v = g_acc[n * NC + c];
    const __nv_bfloat16* hr = g_hb + (size_t)n * NF;
#pragma unroll
    for (int h = 0; h < NH; ++h) {
        float a = g_asrc[n * NH + h] + g_adst[n * NH + h];
        a = a > 0.f ? a : 0.2f * a;
        float w = __expf(a) * g_s[n * NH + h];   // g_s holds 1/s
        v = fmaf(0.125f * w, __bfloat162float(hr[h * 16 + c]), v);
    }
    v += bias[c];
    v = v > 0.f ? v : expm1f(v);
    int b = batch[n];
    atomicAdd(&g_pool[b * NC + c], v);
    if (c == 0) atomicAdd(&g_cnt[b], 1.0f);
}

// ---------------- K7: pooled mean ------------------------------------------
__global__ void k_pool_div(float* __restrict__ out) {
    int i = blockIdx.x * blockDim.x + threadIdx.x;
    if (i < NG * NC) {
        int g = i >> 4;
        out[i] = g_pool[i] / fmaxf(g_cnt[g], 1.0f);
    }
}

// ---------------- launch ----------------------------------------------------
extern "C" void kernel_launch(void* const* d_in, const int* in_sizes, int n_in,
                              void* d_out, int out_size) {
    const float* x = (const float*)d_in[0];
    const int* ei = (const int*)d_in[1];
    const int* batch = (const int*)d_in[2];
    const float* gamma = (const float*)d_in[3];
    const float* beta = (const float*)d_in[4];
    const float* W = (const float*)d_in[5];
    const float* attS = (const float*)d_in[6];
    const float* attD = (const float*)d_in[7];
    const float* bias = (const float*)d_in[8];
    float* out = (float*)d_out;

    cudaFuncSetAttribute(k_gemm, cudaFuncAttributeMaxDynamicSharedMemorySize,
                         GEMM_SMEM_BYTES);

    k_zero_stats<<<1, 128>>>();
    k_stats<<<512, 256>>>(x);
    k_prep<<<80, 256>>>(W, gamma, beta);
    k_gemm<<<(NN + 127) / 128, 256, GEMM_SMEM_BYTES>>>(x, attS, attD);
    k_edge_s<<<(NE + 255) / 256, 256>>>(ei);
    k_sinv<<<(NN * 4 + 255) / 256, 256>>>();
    k_edge_msg<<<(NE * 4 + 255) / 256, 256>>>(ei);
    k_node_final<<<(NN * 16 + 255) / 256, 256>>>(batch, bias);
    k_pool_div<<<(NG * NC + 255) / 256, 256>>>(out);
}

// round 14
// speedup vs baseline: 1.3057x; 1.0294x over previous
#include <cuda_runtime.h>
#include <cuda_bf16.h>
#include <cuda_fp16.h>
#include <math.h>

#define NN 100000
#define NE 1600000
#define NG 100
#define NH 8
#define NC 16
#define NF 128

// ---------------- scratch (static device globals) ---------------------------
__device__ __align__(16) __nv_bfloat16 g_hb[(size_t)NN * NF];  // 25.6 MB h (bf16)
__device__ __align__(16) __half g_w[(size_t)NE * NH];          // 25.6 MB edge weights
__device__ __align__(16) float g_asrc[NN * NH];
__device__ __align__(16) float g_adst[NN * NH];
__device__ __align__(16) float g_s[NN * NH];           // softmax denom, then inverted
__device__ __align__(16) float g_acc[NN * NC];         // head-averaged message accum
__device__ __align__(16) float g_colsum[NF];
__device__ __align__(16) float g_colsq[NF];
__device__ __align__(16) float g_Wp[NF * NF];          // BN-folded weights
__device__ __align__(16) float g_bp[NF];               // BN-folded bias
__device__ __align__(16) float g_pool[NG * NC];
__device__ __align__(16) float g_cnt[NG];

// vector reduction (no return) ----------------------------------------------
__device__ __forceinline__ void red_v4(float* p, float a, float b, float c, float d) {
    asm volatile("red.global.add.v4.f32 [%0], {%1, %2, %3, %4};"
                 :: "l"(p), "f"(a), "f"(b), "f"(c), "f"(d) : "memory");
}

__device__ __forceinline__ unsigned f2tf32(float f) {
    unsigned r;
    asm("cvt.rna.tf32.f32 %0, %1;" : "=r"(r) : "f"(f));
    return r;
}

__device__ __forceinline__ void bn_coeff(int k, const float* gamma, const float* beta,
                                         float& sc, float& sh) {
    float mean = g_colsum[k] * (1.f / NN);
    float var = g_colsq[k] * (1.f / NN) - mean * mean;
    sc = gamma[k] * rsqrtf(var + 1e-5f);
    sh = beta[k] - mean * sc;
}

// ---------------- K0b: zero colsum/colsq ------------------------------------
__global__ void k_zero_stats() {
    int i = threadIdx.x;
    if (i < NF) { g_colsum[i] = 0.f; g_colsq[i] = 0.f; }
}

// ---------------- K1: BN column stats + zero accumulators -------------------
__global__ void k_stats(const float* __restrict__ x) {
    __shared__ float ssum[NF];
    __shared__ float ssq[NF];
    int t = threadIdx.x;
    int lane = t & 31;
    int warp = t >> 5;
    int col = lane * 4;
    if (t < NF) { ssum[t] = 0.f; ssq[t] = 0.f; }
    __syncthreads();

    // zero accumulators (grid-stride over 512 blocks)
    int gi = blockIdx.x * blockDim.x + t;
    int gst = gridDim.x * blockDim.x;
    for (int k = gi; k < NN * NC; k += gst) g_acc[k] = 0.f;
    if (gi < NG * NC) g_pool[gi] = 0.f;
    if (gi < NG) g_cnt[gi] = 0.f;

    float s0 = 0.f, s1 = 0.f, s2 = 0.f, s3 = 0.f;
    float q0 = 0.f, q1 = 0.f, q2 = 0.f, q3 = 0.f;
    int row = blockIdx.x * 8 + warp;
    int step = gridDim.x * 8;
    for (int r = row; r < NN; r += step) {
        float4 v = *(const float4*)(x + (size_t)r * NF + col);
        s0 += v.x; s1 += v.y; s2 += v.z; s3 += v.w;
        q0 += v.x * v.x; q1 += v.y * v.y; q2 += v.z * v.z; q3 += v.w * v.w;
    }
    atomicAdd(&ssum[col + 0], s0); atomicAdd(&ssum[col + 1], s1);
    atomicAdd(&ssum[col + 2], s2); atomicAdd(&ssum[col + 3], s3);
    atomicAdd(&ssq[col + 0], q0);  atomicAdd(&ssq[col + 1], q1);
    atomicAdd(&ssq[col + 2], q2);  atomicAdd(&ssq[col + 3], q3);
    __syncthreads();
    if (t < NF) {
        atomicAdd(&g_colsum[t], ssum[t]);
        atomicAdd(&g_colsq[t], ssq[t]);
    }
}

// ---------------- K2b: fold BN into weights (BN coeffs inline) --------------
__global__ void k_prep(const float* __restrict__ W,
                       const float* __restrict__ gamma,
                       const float* __restrict__ beta) {
    if (blockIdx.x < 64) {
        __shared__ float ssc[2];
        int k0 = blockIdx.x * 2;
        if (threadIdx.x < 2) {
            float sc, sh;
            bn_coeff(k0 + threadIdx.x, gamma, beta, sc, sh);
            ssc[threadIdx.x] = sc;
        }
        __syncthreads();
        int i = blockIdx.x * 256 + threadIdx.x;
        int k = (i >> 7) - k0;
        g_Wp[i] = ssc[k] * W[i];
    } else {
        __shared__ float ssh[NF];
        if (threadIdx.x < NF) {
            float sc, sh;
            bn_coeff(threadIdx.x, gamma, beta, sc, sh);
            ssh[threadIdx.x] = sh;
        }
        __syncthreads();
        int j = (blockIdx.x - 64) * 8 + (threadIdx.x >> 5);
        int lane = threadIdx.x & 31;
        float b = 0.f;
#pragma unroll
        for (int k = lane; k < NF; k += 32)
            b = fmaf(ssh[k], W[k * NF + j], b);
        b += __shfl_xor_sync(0xffffffffu, b, 16);
        b += __shfl_xor_sync(0xffffffffu, b, 8);
        b += __shfl_xor_sync(0xffffffffu, b, 4);
        b += __shfl_xor_sync(0xffffffffu, b, 2);
        b += __shfl_xor_sync(0xffffffffu, b, 1);
        if (lane == 0) g_bp[j] = b;
    }
}

// ---------------- K3: tensor-core GEMM x@W' + b' + logits -------------------
#define XS_STRIDE 36
#define WS_STRIDE 136
#define XCHUNK_FLOATS (128 * XS_STRIDE)
#define WSM_FLOATS (NF * WS_STRIDE)
#define GEMM_SMEM_BYTES ((WSM_FLOATS + 2 * XCHUNK_FLOATS) * 4)

#define MMA_TF32(d, a, b)                                                     \
    asm volatile(                                                             \
        "mma.sync.aligned.m16n8k8.row.col.f32.tf32.tf32.f32 "                 \
        "{%0,%1,%2,%3}, {%4,%5,%6,%7}, {%8,%9}, {%0,%1,%2,%3};"               \
        : "+f"(d[0]), "+f"(d[1]), "+f"(d[2]), "+f"(d[3])                      \
        : "r"(a[0]), "r"(a[1]), "r"(a[2]), "r"(a[3]), "r"(b[0]), "r"(b[1]))

__device__ __forceinline__ void cp16(void* dst_smem, const void* src, int sz) {
    unsigned d = (unsigned)__cvta_generic_to_shared(dst_smem);
    asm volatile("cp.async.cg.shared.global [%0], [%1], 16, %2;"
                 :: "r"(d), "l"(src), "r"(sz));
}
#define CP_COMMIT() asm volatile("cp.async.commit_group;")

__global__ void __launch_bounds__(256, 2)
k_gemm(const float* __restrict__ x,
       const float* __restrict__ attS, const float* __restrict__ attD) {
    extern __shared__ float smem[];
    float* Wsm = smem;                       // [k][n] stride 136 (tf32 bits)
    float* Xs0 = smem + WSM_FLOATS;          // [row][k] stride 36 (raw fp32)
    float* Xs1 = Xs0 + XCHUNK_FLOATS;

    int t = threadIdx.x;
    int lane = t & 31;
    int wid = t >> 5;
    int g = lane >> 2, tg = lane & 3;
    int wm = wid & 1, wn = wid >> 1;
    int r0 = blockIdx.x * 128;

    // issue x chunk 0
#pragma unroll
    for (int p = 0; p < 4; ++p) {
        int idx = t + p * 256;
        int row = idx >> 3, grp = idx & 7;
        int n = r0 + row;
        cp16(Xs0 + row * XS_STRIDE + grp * 4,
             x + (size_t)n * NF + grp * 4, (n < NN) ? 16 : 0);
    }
    CP_COMMIT();

    // stage W' whole, rna-converted at staging
#pragma unroll
    for (int p = 0; p < 16; ++p) {
        int i = t + p * 256;
        int row = i >> 5, grp = i & 31;
        float4 v = ((const float4*)(g_Wp + row * NF))[grp];
        unsigned* dst = (unsigned*)(Wsm + row * WS_STRIDE + grp * 4);
        dst[0] = f2tf32(v.x); dst[1] = f2tf32(v.y);
        dst[2] = f2tf32(v.z); dst[3] = f2tf32(v.w);
    }

    float acc[4][4][4];
#pragma unroll
    for (int i = 0; i < 4; ++i)
#pragma unroll
        for (int j = 0; j < 4; ++j)
#pragma unroll
            for (int c = 0; c < 4; ++c) acc[i][j][c] = 0.f;

#pragma unroll
    for (int kc = 0; kc < 4; ++kc) {
        if (kc < 3) {
            float* Xs = (kc & 1) ? Xs0 : Xs1;
            int kbase = (kc + 1) * 32;
#pragma unroll
            for (int p = 0; p < 4; ++p) {
                int idx = t + p * 256;
                int row = idx >> 3, grp = idx & 7;
                int n = r0 + row;
                cp16(Xs + row * XS_STRIDE + grp * 4,
                     x + (size_t)n * NF + kbase + grp * 4, (n < NN) ? 16 : 0);
            }
            CP_COMMIT();
            asm volatile("cp.async.wait_group 1;");
        } else {
            asm volatile("cp.async.wait_group 0;");
        }
        __syncthreads();

        const float* Xs = (kc & 1) ? Xs1 : Xs0;
#pragma unroll
        for (int ks = 0; ks < 4; ++ks) {
            int k = ks * 8;
            unsigned a[4][4], b[4][2];
#pragma unroll
            for (int i = 0; i < 4; ++i) {
                int rlo = wm * 64 + i * 16 + g;
                a[i][0] = f2tf32(Xs[rlo * XS_STRIDE + k + tg]);
                a[i][1] = f2tf32(Xs[(rlo + 8) * XS_STRIDE + k + tg]);
                a[i][2] = f2tf32(Xs[rlo * XS_STRIDE + k + tg + 4]);
                a[i][3] = f2tf32(Xs[(rlo + 8) * XS_STRIDE + k + tg + 4]);
            }
#pragma unroll
            for (int j = 0; j < 4; ++j) {
                int c = wn * 32 + j * 8 + g;
                b[j][0] = __float_as_uint(Wsm[(kc * 32 + k + tg) * WS_STRIDE + c]);
                b[j][1] = __float_as_uint(Wsm[(kc * 32 + k + tg + 4) * WS_STRIDE + c]);
            }
#pragma unroll
            for (int i = 0; i < 4; ++i)
#pragma unroll
                for (int j = 0; j < 4; ++j) MMA_TF32(acc[i][j], a[i], b[j]);
        }
        __syncthreads();
    }

    int rowsValid = NN - r0;
    if (rowsValid > 128) rowsValid = 128;

    // add folded-BN bias b'[col]
#pragma unroll
    for (int j = 0; j < 4; ++j) {
        int c0 = wn * 32 + j * 8 + 2 * tg;
        float b0 = g_bp[c0], b1 = g_bp[c0 + 1];
#pragma unroll
        for (int i = 0; i < 4; ++i) {
            acc[i][j][0] += b0; acc[i][j][1] += b1;
            acc[i][j][2] += b0; acc[i][j][3] += b1;
        }
    }

    // store h tile as bf16 from fragments
#pragma unroll
    for (int i = 0; i < 4; ++i) {
        int rlo = wm * 64 + i * 16 + g;
        int rhi = rlo + 8;
#pragma unroll
        for (int j = 0; j < 4; ++j) {
            int c0 = wn * 32 + j * 8 + 2 * tg;
            if (rlo < rowsValid) {
                __nv_bfloat162 p = __float22bfloat162_rn(
                    make_float2(acc[i][j][0], acc[i][j][1]));
                *(__nv_bfloat162*)(g_hb + (size_t)(r0 + rlo) * NF + c0) = p;
            }
            if (rhi < rowsValid) {
                __nv_bfloat162 p = __float22bfloat162_rn(
                    make_float2(acc[i][j][2], acc[i][j][3]));
                *(__nv_bfloat162*)(g_hb + (size_t)(r0 + rhi) * NF + c0) = p;
            }
        }
    }

    // attention logits: warp covers heads {2wn, 2wn+1}; quad-reduce over tg
    float aS[2][2][2], aD[2][2][2];
#pragma unroll
    for (int hl = 0; hl < 2; ++hl)
#pragma unroll
        for (int j2 = 0; j2 < 2; ++j2) {
            int base = (2 * wn + hl) * 16 + j2 * 8 + 2 * tg;
            aS[hl][j2][0] = attS[base];     aS[hl][j2][1] = attS[base + 1];
            aD[hl][j2][0] = attD[base];     aD[hl][j2][1] = attD[base + 1];
        }

#pragma unroll
    for (int i = 0; i < 4; ++i) {
#pragma unroll
        for (int hl = 0; hl < 2; ++hl) {
            float psl = 0.f, pdl = 0.f, psh = 0.f, pdh = 0.f;
#pragma unroll
            for (int j2 = 0; j2 < 2; ++j2) {
                int j = 2 * hl + j2;
                psl = fmaf(acc[i][j][0], aS[hl][j2][0],
                      fmaf(acc[i][j][1], aS[hl][j2][1], psl));
                pdl = fmaf(acc[i][j][0], aD[hl][j2][0],
                      fmaf(acc[i][j][1], aD[hl][j2][1], pdl));
                psh = fmaf(acc[i][j][2], aS[hl][j2][0],
                      fmaf(acc[i][j][3], aS[hl][j2][1], psh));
                pdh = fmaf(acc[i][j][2], aD[hl][j2][0],
                      fmaf(acc[i][j][3], aD[hl][j2][1], pdh));
            }
            psl += __shfl_xor_sync(0xffffffffu, psl, 1);
            psl += __shfl_xor_sync(0xffffffffu, psl, 2);
            pdl += __shfl_xor_sync(0xffffffffu, pdl, 1);
            pdl += __shfl_xor_sync(0xffffffffu, pdl, 2);
            psh += __shfl_xor_sync(0xffffffffu, psh, 1);
            psh += __shfl_xor_sync(0xffffffffu, psh, 2);
            pdh += __shfl_xor_sync(0xffffffffu, pdh, 1);
            pdh += __shfl_xor_sync(0xffffffffu, pdh, 2);
            if (tg == 0) {
                int h = 2 * wn + hl;
                int rlo = wm * 64 + i * 16 + g;
                int rhi = rlo + 8;
                if (rlo < rowsValid) {
                    int n = r0 + rlo;
                    g_asrc[n * NH + h] = psl;
                    g_adst[n * NH + h] = pdl;
                    float e = psl + pdl;
                    e = e > 0.f ? e : 0.2f * e;
                    g_s[n * NH + h] = __expf(e);
                }
                if (rhi < rowsValid) {
                    int n = r0 + rhi;
                    g_asrc[n * NH + h] = psh;
                    g_adst[n * NH + h] = pdh;
                    float e = psh + pdh;
                    e = e > 0.f ? e : 0.2f * e;
                    g_s[n * NH + h] = __expf(e);
                }
            }
        }
    }
}

// ---------------- K4: edge pass 1 — weights + denominators -----------------
__device__ __forceinline__ float lrelu_exp(float a, float b) {
    float e = a + b;
    e = e > 0.f ? e : 0.2f * e;
    return __expf(e);
}

__global__ void k_edge_s(const int* __restrict__ ei) {
    int e = blockIdx.x * blockDim.x + threadIdx.x;
    if (e >= NE) return;
    int s = ei[e];
    int d = ei[NE + e];
    float4 a0 = *(const float4*)(g_asrc + s * NH);
    float4 a1 = *(const float4*)(g_asrc + s * NH + 4);
    float4 b0 = *(const float4*)(g_adst + d * NH);
    float4 b1 = *(const float4*)(g_adst + d * NH + 4);
    float w0 = lrelu_exp(a0.x, b0.x), w1 = lrelu_exp(a0.y, b0.y);
    float w2 = lrelu_exp(a0.z, b0.z), w3 = lrelu_exp(a0.w, b0.w);
    float w4 = lrelu_exp(a1.x, b1.x), w5 = lrelu_exp(a1.y, b1.y);
    float w6 = lrelu_exp(a1.z, b1.z), w7 = lrelu_exp(a1.w, b1.w);
    // store per-edge weights as half8 (16B coalesced)
    __half2 hw[4];
    hw[0] = __floats2half2_rn(w0, w1);
    hw[1] = __floats2half2_rn(w2, w3);
    hw[2] = __floats2half2_rn(w4, w5);
    hw[3] = __floats2half2_rn(w6, w7);
    *(uint4*)(g_w + (size_t)e * NH) = *(uint4*)hw;
    float* sp = g_s + d * NH;
    red_v4(sp, w0, w1, w2, w3);
    red_v4(sp + 4, w4, w5, w6, w7);
}

// ---------------- K4b: invert denominators ---------------------------------
__global__ void k_sinv() {
    int i = blockIdx.x * blockDim.x + threadIdx.x;
    if (i < NN * NH) g_s[i] = __frcp_rn(g_s[i]);
}

// ---------------- K5: edge pass 2 — message scatter (4 threads/edge) -------
// Thread q: coalesced half2 w pair + sinv pair gather (8B) + h gather (8B).
// No exp, no asrc/adst gathers.
__global__ void k_edge_msg(const int* __restrict__ ei) {
    int gt = blockIdx.x * blockDim.x + threadIdx.x;
    int e = gt >> 2, q = gt & 3;
    if (e >= NE) return;
    int s = ei[e];
    int d = ei[NE + e];

    __half2 w2 = *(const __half2*)(g_w + (size_t)e * NH + q * 2);  // coalesced
    float2 wf = __half22float2(w2);
    float2 si2 = *(const float2*)(g_s + d * NH + q * 2);           // gather 8B
    float2 alq;
    alq.x = 0.125f * wf.x * si2.x;
    alq.y = 0.125f * wf.y * si2.y;

    unsigned long long v0 = *(unsigned long long*)&alq;
    unsigned long long v1 = __shfl_xor_sync(0xffffffffu, v0, 1);
    unsigned long long v2 = __shfl_xor_sync(0xffffffffu, v0, 2);
    unsigned long long v3 = __shfl_xor_sync(0xffffffffu, v1, 2);
    float2 p1 = *(float2*)&v1, p2 = *(float2*)&v2, p3 = *(float2*)&v3;

    float al[8];
#pragma unroll
    for (int i = 0; i < 4; ++i) {
        int r = i ^ q;
        float2 p = (r == 0) ? alq : (r == 1) ? p1 : (r == 2) ? p2 : p3;
        al[2 * i] = p.x;
        al[2 * i + 1] = p.y;
    }

    const __nv_bfloat16* hrow = g_hb + (size_t)s * NF + q * 4;
    float r0 = 0.f, r1 = 0.f, r2 = 0.f, r3 = 0.f;
#pragma unroll
    for (int h = 0; h < NH; ++h) {
        __nv_bfloat162 p01 = *(const __nv_bfloat162*)(hrow + h * 16);
        __nv_bfloat162 p23 = *(const __nv_bfloat162*)(hrow + h * 16 + 2);
        float2 f01 = __bfloat1622float2(p01);
        float2 f23 = __bfloat1622float2(p23);
        r0 = fmaf(al[h], f01.x, r0);
        r1 = fmaf(al[h], f01.y, r1);
        r2 = fmaf(al[h], f23.x, r2);
        r3 = fmaf(al[h], f23.y, r3);
    }
    red_v4(g_acc + d * NC + q * 4, r0, r1, r2, r3);
}

// ---------------- K6: node finalize (self-loop + bias + ELU + pool) --------
__global__ void k_node_final(const int* __restrict__ batch,
                             const float* __restrict__ bias) {
    int gt = blockIdx.x * blockDim.x + threadIdx.x;
    int n = gt >> 4, c = gt & 15;
    if (n >= NN) return;
    float v = g_acc[n * NC + c];
    const __nv_bfloat16* hr = g_hb + (size_t)n * NF;
#pragma unroll
    for (int h = 0; h < NH; ++h) {
        float a = g_asrc[n * NH + h] + g_adst[n * NH + h];
        a = a > 0.f ? a : 0.2f * a;
        float w = __expf(a) * g_s[n * NH + h];   // g_s holds 1/s
        v = fmaf(0.125f * w, __bfloat162float(hr[h * 16 + c]), v);
    }
    v += bias[c];
    v = v > 0.f ? v : expm1f(v);
    int b = batch[n];
    atomicAdd(&g_pool[b * NC + c], v);
    if (c == 0) atomicAdd(&g_cnt[b], 1.0f);
}

// ---------------- K7: pooled mean ------------------------------------------
__global__ void k_pool_div(float* __restrict__ out) {
    int i = blockIdx.x * blockDim.x + threadIdx.x;
    if (i < NG * NC) {
        int g = i >> 4;
        out[i] = g_pool[i] / fmaxf(g_cnt[g], 1.0f);
    }
}

// ---------------- launch ----------------------------------------------------
extern "C" void kernel_launch(void* const* d_in, const int* in_sizes, int n_in,
                              void* d_out, int out_size) {
    const float* x = (const float*)d_in[0];
    const int* ei = (const int*)d_in[1];
    const int* batch = (const int*)d_in[2];
    const float* gamma = (const float*)d_in[3];
    const float* beta = (const float*)d_in[4];
    const float* W = (const float*)d_in[5];
    const float* attS = (const float*)d_in[6];
    const float* attD = (const float*)d_in[7];
    const float* bias = (const float*)d_in[8];
    float* out = (float*)d_out;

    cudaFuncSetAttribute(k_gemm, cudaFuncAttributeMaxDynamicSharedMemorySize,
                         GEMM_SMEM_BYTES);

    k_zero_stats<<<1, 128>>>();
    k_stats<<<512, 256>>>(x);
    k_prep<<<80, 256>>>(W, gamma, beta);
    k_gemm<<<(NN + 127) / 128, 256, GEMM_SMEM_BYTES>>>(x, attS, attD);
    k_edge_s<<<(NE + 255) / 256, 256>>>(ei);
    k_sinv<<<(NN * NH + 255) / 256, 256>>>();
    k_edge_msg<<<(NE * 4 + 255) / 256, 256>>>(ei);
    k_node_final<<<(NN * 16 + 255) / 256, 256>>>(batch, bias);
    k_pool_div<<<(NG * NC + 255) / 256, 256>>>(out);
}